// round 1
// baseline (speedup 1.0000x reference)
#include <cuda_runtime.h>
#include <cuda_bf16.h>
#include <cstdint>

// Problem constants
#define B_ 4
#define T_ 2048
#define DIM_ 2048
#define H_ 16
#define QLORA_ 1536
#define KVLORA_ 512
#define ROPE_D_ 64
#define NOPE_D_ 128
#define V_D_ 128
#define QHEAD_D_ 192
#define MTOK (B_ * T_)   // 8192

// ---------------- scratch (device globals; no runtime allocation) -------------
__device__ float g_cq[(size_t)MTOK * QLORA_];          // 8192x1536
__device__ float g_q[(size_t)MTOK * H_ * QHEAD_D_];    // 8192x3072 (assembled, roped)
__device__ float g_kvraw[(size_t)MTOK * 576];          // 8192x576
__device__ float g_ckv[(size_t)MTOK * KVLORA_];        // 8192x512 (normed)
__device__ float g_krope[(size_t)MTOK * ROPE_D_];      // 8192x64 (roped, shared across heads)
__device__ float g_kv[(size_t)MTOK * 4096];            // 8192x4096: per head [k_nope(128) | v(128)]
__device__ float g_attno[(size_t)MTOK * (H_ * V_D_)];  // 8192x2048

// ---------------- block reduce -------------------------------------------------
__device__ __forceinline__ float block_reduce_sum_256(float v) {
    __shared__ float red[8];
    int lane = threadIdx.x & 31, w = threadIdx.x >> 5;
#pragma unroll
    for (int o = 16; o; o >>= 1) v += __shfl_xor_sync(0xffffffffu, v, o);
    if (lane == 0) red[w] = v;
    __syncthreads();
    if (w == 0) {
        v = (lane < 8) ? red[lane] : 0.f;
#pragma unroll
        for (int o = 4; o; o >>= 1) v += __shfl_xor_sync(0xffffffffu, v, o);
        if (lane == 0) red[0] = v;
    }
    __syncthreads();
    return red[0];
}

// ---------------- generic SGEMM: C[m, map(n)] = sum_k A[m,k] * W[n,k] ----------
// A: [M,K] row-major, W: [N,K] row-major (all projection weights are (out,in)).
// Output column mapping: col = (n/group)*head_stride + n%group + col_off
//   plain gemm: group=N, head_stride=0, col_off=0  -> col = n
#define BM 128
#define BN 128
#define BKK 8

__global__ void __launch_bounds__(256) sgemm_nt(
    const float* __restrict__ A, const float* __restrict__ W,
    float* __restrict__ C, int M, int N, int K,
    int ldc, int group, int head_stride, int col_off)
{
    __shared__ float As[BKK][BM];
    __shared__ float Ws[BKK][BN];
    int tid = threadIdx.x;
    int bm = blockIdx.y * BM;
    int bn = blockIdx.x * BN;
    int tx = tid & 15, ty = tid >> 4;
    int lr = tid >> 1;          // 0..127
    int lc = (tid & 1) * 4;     // 0 or 4

    float acc[8][8];
#pragma unroll
    for (int i = 0; i < 8; i++)
#pragma unroll
        for (int j = 0; j < 8; j++) acc[i][j] = 0.f;

    const float* Aptr = A + (size_t)(bm + lr) * K + lc;
    int wn = bn + lr;
    const float* Wptr = W + (size_t)wn * K + lc;
    bool wvalid = wn < N;

    for (int k0 = 0; k0 < K; k0 += BKK) {
        float4 a = *(const float4*)(Aptr + k0);
        float4 b = wvalid ? *(const float4*)(Wptr + k0) : make_float4(0.f, 0.f, 0.f, 0.f);
        As[lc + 0][lr] = a.x; As[lc + 1][lr] = a.y; As[lc + 2][lr] = a.z; As[lc + 3][lr] = a.w;
        Ws[lc + 0][lr] = b.x; Ws[lc + 1][lr] = b.y; Ws[lc + 2][lr] = b.z; Ws[lc + 3][lr] = b.w;
        __syncthreads();
#pragma unroll
        for (int kk = 0; kk < BKK; kk++) {
            float4 a0 = *(const float4*)&As[kk][ty * 8];
            float4 a1 = *(const float4*)&As[kk][ty * 8 + 4];
            float4 b0 = *(const float4*)&Ws[kk][tx * 8];
            float4 b1 = *(const float4*)&Ws[kk][tx * 8 + 4];
            float ra[8] = {a0.x, a0.y, a0.z, a0.w, a1.x, a1.y, a1.z, a1.w};
            float rb[8] = {b0.x, b0.y, b0.z, b0.w, b1.x, b1.y, b1.z, b1.w};
#pragma unroll
            for (int i = 0; i < 8; i++)
#pragma unroll
                for (int j = 0; j < 8; j++)
                    acc[i][j] = fmaf(ra[i], rb[j], acc[i][j]);
        }
        __syncthreads();
    }

#pragma unroll
    for (int i = 0; i < 8; i++) {
        int row = bm + ty * 8 + i;
#pragma unroll
        for (int j = 0; j < 8; j++) {
            int n = bn + tx * 8 + j;
            if (n < N) {
                int g = n / group;
                int col = g * head_stride + (n - g * group) + col_off;
                C[(size_t)row * ldc + col] = acc[i][j];
            }
        }
    }
}

// ---------------- rmsnorm in place (D = 1536), w applied -----------------------
__global__ void rmsnorm_kernel(float* __restrict__ xio, const float* __restrict__ w, int D) {
    size_t row = blockIdx.x;
    float* p = xio + row * (size_t)D;
    float ss = 0.f;
    for (int i = threadIdx.x; i < D; i += 256) { float v = p[i]; ss += v * v; }
    ss = block_reduce_sum_256(ss);
    float r = rsqrtf(ss / (float)D + 1e-6f);
    for (int i = threadIdx.x; i < D; i += 256) p[i] = p[i] * r * w[i];
}

// ---------------- kv prep: rmsnorm first 512 -> g_ckv; rope last 64 -> g_krope -
__global__ void kvprep_kernel(const float* __restrict__ raw, const float* __restrict__ w,
                              const float* __restrict__ fc, const float* __restrict__ fs,
                              float* __restrict__ ckv, float* __restrict__ kr) {
    int tok = blockIdx.x;
    const float* src = raw + (size_t)tok * 576;
    float ss = 0.f;
    for (int i = threadIdx.x; i < 512; i += 256) { float v = src[i]; ss += v * v; }
    ss = block_reduce_sum_256(ss);
    float r = rsqrtf(ss / 512.f + 1e-6f);
    for (int i = threadIdx.x; i < 512; i += 256)
        ckv[(size_t)tok * 512 + i] = src[i] * r * w[i];
    if (threadIdx.x < 32) {
        int t = tok & (T_ - 1);
        int i = threadIdx.x;
        float x0 = src[512 + 2 * i], x1 = src[512 + 2 * i + 1];
        float c = fc[t * 32 + i], s = fs[t * 32 + i];
        kr[(size_t)tok * 64 + 2 * i]     = x0 * c - x1 * s;
        kr[(size_t)tok * 64 + 2 * i + 1] = x0 * s + x1 * c;
    }
}

// ---------------- rope q in place (dims 128..191 of each head) -----------------
__global__ void rope_q_kernel(float* __restrict__ q, const float* __restrict__ fc,
                              const float* __restrict__ fs) {
    int tok = blockIdx.x;
    int t = tok & (T_ - 1);
    int p = threadIdx.x;      // 512 threads: 16 heads x 32 pairs
    int h = p >> 5, i = p & 31;
    float* b = q + (size_t)tok * 3072 + h * 192 + 128;
    float x0 = b[2 * i], x1 = b[2 * i + 1];
    float c = fc[t * 32 + i], s = fs[t * 32 + i];
    b[2 * i]     = x0 * c - x1 * s;
    b[2 * i + 1] = x0 * s + x1 * c;
}

// ---------------- flash attention (fp32, causal) -------------------------------
// Br=Bc=64, 256 threads (16x16). S microtile 4x4/thread, O microtile 4x8/thread.
// K stored d-major in smem (stride 65: conflict-free transposed write).
#define QS 196    // 192 + 4 pad
#define KS 65     // 64 + 1 pad
#define VS 128
#define PS 68     // 64 + 4 pad
#define ATT_SMEM_FLOATS (64 * QS + 192 * KS + 64 * VS + 64 * PS)
#define ATT_SMEM_BYTES (ATT_SMEM_FLOATS * 4)

__global__ void __launch_bounds__(256) attn_kernel(
    const float* __restrict__ q, const float* __restrict__ kv,
    const float* __restrict__ krope, float* __restrict__ out)
{
    extern __shared__ float sm[];
    float* sQ  = sm;                       // [64][QS]  q (nope|rope), row-major
    float* sKt = sQ + 64 * QS;             // [192][KS] k d-major (nope rows 0..127, rope 128..191)
    float* sV  = sKt + 192 * KS;           // [64][VS]
    float* sP  = sV + 64 * VS;             // [64][PS]

    int b = blockIdx.z, h = blockIdx.y, qt = blockIdx.x;
    int tid = threadIdx.x;
    int tx = tid & 15, ty = tid >> 4;
    int t0 = b * T_ + qt * 64;

    // load Q tile [64 x 192]
    for (int idx = tid; idx < 64 * 192; idx += 256) {
        int r = idx / 192, d = idx - r * 192;
        sQ[r * QS + d] = q[(size_t)(t0 + r) * 3072 + h * 192 + d];
    }

    float m[4], l[4], acc[4][8];
#pragma unroll
    for (int i = 0; i < 4; i++) {
        m[i] = -1e30f; l[i] = 0.f;
#pragma unroll
        for (int j = 0; j < 8; j++) acc[i][j] = 0.f;
    }
    const float scale = 0.07216878364870323f;  // 1/sqrt(192)

    for (int jt = 0; jt <= qt; jt++) {
        int kb = b * T_ + jt * 64;
        __syncthreads();   // previous iter done with sKt/sV/sP; also orders sQ writes
        // load K (nope, transposed) + V
        for (int idx = tid; idx < 64 * 128; idx += 256) {
            int c = idx >> 7, d = idx & 127;
            size_t base = (size_t)(kb + c) * 4096 + h * 256;
            sKt[d * KS + c] = kv[base + d];
            sV[c * VS + d]  = kv[base + 128 + d];
        }
        // load K rope (shared across heads), transposed into rows 128..191
        for (int idx = tid; idx < 64 * 64; idx += 256) {
            int c = idx >> 6, d = idx & 63;
            sKt[(128 + d) * KS + c] = krope[(size_t)(kb + c) * 64 + d];
        }
        __syncthreads();

        // S = Q K^T  (4x4 per thread)
        float s[4][4];
#pragma unroll
        for (int i = 0; i < 4; i++)
#pragma unroll
            for (int j = 0; j < 4; j++) s[i][j] = 0.f;
        for (int d = 0; d < 192; d++) {
            float qv[4], kvv[4];
#pragma unroll
            for (int i = 0; i < 4; i++) qv[i] = sQ[(ty * 4 + i) * QS + d];
#pragma unroll
            for (int j = 0; j < 4; j++) kvv[j] = sKt[d * KS + tx * 4 + j];
#pragma unroll
            for (int i = 0; i < 4; i++)
#pragma unroll
                for (int j = 0; j < 4; j++) s[i][j] = fmaf(qv[i], kvv[j], s[i][j]);
        }
        // scale + causal mask (diagonal tile only)
        bool diag = (jt == qt);
#pragma unroll
        for (int i = 0; i < 4; i++)
#pragma unroll
            for (int j = 0; j < 4; j++) {
                s[i][j] *= scale;
                if (diag && (tx * 4 + j) > (ty * 4 + i)) s[i][j] = -1e30f;
            }
        // online softmax update
#pragma unroll
        for (int i = 0; i < 4; i++) {
            float v = fmaxf(fmaxf(s[i][0], s[i][1]), fmaxf(s[i][2], s[i][3]));
#pragma unroll
            for (int o = 8; o; o >>= 1) v = fmaxf(v, __shfl_xor_sync(0xffffffffu, v, o));
            float mn = fmaxf(m[i], v);
            float alpha = __expf(m[i] - mn);
            m[i] = mn;
            float sum = 0.f;
#pragma unroll
            for (int j = 0; j < 4; j++) {
                float p = __expf(s[i][j] - mn);
                sP[(ty * 4 + i) * PS + tx * 4 + j] = p;
                sum += p;
            }
#pragma unroll
            for (int o = 8; o; o >>= 1) sum += __shfl_xor_sync(0xffffffffu, sum, o);
            l[i] = l[i] * alpha + sum;
#pragma unroll
            for (int j = 0; j < 8; j++) acc[i][j] *= alpha;
        }
        __syncthreads();
        // O += P V   (4x8 per thread)
        for (int c = 0; c < 64; c++) {
            float4 v0 = *(const float4*)&sV[c * VS + tx * 8];
            float4 v1 = *(const float4*)&sV[c * VS + tx * 8 + 4];
#pragma unroll
            for (int i = 0; i < 4; i++) {
                float p = sP[(ty * 4 + i) * PS + c];
                acc[i][0] = fmaf(p, v0.x, acc[i][0]);
                acc[i][1] = fmaf(p, v0.y, acc[i][1]);
                acc[i][2] = fmaf(p, v0.z, acc[i][2]);
                acc[i][3] = fmaf(p, v0.w, acc[i][3]);
                acc[i][4] = fmaf(p, v1.x, acc[i][4]);
                acc[i][5] = fmaf(p, v1.y, acc[i][5]);
                acc[i][6] = fmaf(p, v1.z, acc[i][6]);
                acc[i][7] = fmaf(p, v1.w, acc[i][7]);
            }
        }
    }

    // write normalized output: [tok][h*128 + dv]
#pragma unroll
    for (int i = 0; i < 4; i++) {
        float inv = 1.f / l[i];
        size_t base = (size_t)(t0 + ty * 4 + i) * 2048 + h * 128 + tx * 8;
#pragma unroll
        for (int j = 0; j < 8; j++) out[base + j] = acc[i][j] * inv;
    }
}

// ---------------- launch -------------------------------------------------------
extern "C" void kernel_launch(void* const* d_in, const int* in_sizes, int n_in,
                              void* d_out, int out_size) {
    const float* x           = (const float*)d_in[0];
    const float* fc          = (const float*)d_in[1];
    const float* fs          = (const float*)d_in[2];
    // d_in[3] = mask (causal, implemented directly)
    const float* q_down_w    = (const float*)d_in[4];
    const float* q_norm_w    = (const float*)d_in[5];
    const float* q_up_nope_w = (const float*)d_in[6];
    const float* q_up_rope_w = (const float*)d_in[7];
    const float* kv_down_w   = (const float*)d_in[8];
    const float* kv_norm_w   = (const float*)d_in[9];
    const float* kv_up_w     = (const float*)d_in[10];
    const float* wo_w        = (const float*)d_in[11];
    float* out = (float*)d_out;

    float *cq, *qbuf, *kvraw, *ckv, *krope, *kvbuf, *attno;
    cudaGetSymbolAddress((void**)&cq,    g_cq);
    cudaGetSymbolAddress((void**)&qbuf,  g_q);
    cudaGetSymbolAddress((void**)&kvraw, g_kvraw);
    cudaGetSymbolAddress((void**)&ckv,   g_ckv);
    cudaGetSymbolAddress((void**)&krope, g_krope);
    cudaGetSymbolAddress((void**)&kvbuf, g_kv);
    cudaGetSymbolAddress((void**)&attno, g_attno);

    dim3 blk(256);
    // q_down: [8192,2048] x [1536,2048] -> g_cq
    sgemm_nt<<<dim3(QLORA_ / 128, MTOK / 128), blk>>>(x, q_down_w, cq,
        MTOK, QLORA_, DIM_, QLORA_, QLORA_, 0, 0);
    rmsnorm_kernel<<<MTOK, 256>>>(cq, q_norm_w, QLORA_);

    // kv_down: N=576 (needs guard)
    sgemm_nt<<<dim3(5, MTOK / 128), blk>>>(x, kv_down_w, kvraw,
        MTOK, 576, DIM_, 576, 576, 0, 0);
    kvprep_kernel<<<MTOK, 256>>>(kvraw, kv_norm_w, fc, fs, ckv, krope);

    // q_up_nope -> g_q[tok, h*192 + 0..127]
    sgemm_nt<<<dim3(2048 / 128, MTOK / 128), blk>>>(cq, q_up_nope_w, qbuf,
        MTOK, 2048, QLORA_, 3072, 128, 192, 0);
    // q_up_rope -> g_q[tok, h*192 + 128..191]
    sgemm_nt<<<dim3(1024 / 128, MTOK / 128), blk>>>(cq, q_up_rope_w, qbuf,
        MTOK, 1024, QLORA_, 3072, 64, 192, 128);
    rope_q_kernel<<<MTOK, 512>>>(qbuf, fc, fs);

    // kv_up: [8192,512] x [4096,512] -> g_kv
    sgemm_nt<<<dim3(4096 / 128, MTOK / 128), blk>>>(ckv, kv_up_w, kvbuf,
        MTOK, 4096, KVLORA_, 4096, 4096, 0, 0);

    // attention
    cudaFuncSetAttribute(attn_kernel, cudaFuncAttributeMaxDynamicSharedMemorySize, ATT_SMEM_BYTES);
    attn_kernel<<<dim3(T_ / 64, H_, B_), 256, ATT_SMEM_BYTES>>>(qbuf, kvbuf, krope, attno);

    // wo: [8192,2048] x [2048,2048] -> out
    sgemm_nt<<<dim3(2048 / 128, MTOK / 128), blk>>>(attno, wo_w, out,
        MTOK, 2048, 2048, 2048, 2048, 0, 0);
}

// round 2
// speedup vs baseline: 2.0940x; 2.0940x over previous
#include <cuda_runtime.h>
#include <cuda_bf16.h>
#include <cstdint>

// Problem constants
#define B_ 4
#define T_ 2048
#define DIM_ 2048
#define H_ 16
#define QLORA_ 1536
#define KVLORA_ 512
#define ROPE_D_ 64
#define NOPE_D_ 128
#define V_D_ 128
#define QHEAD_D_ 192
#define MTOK (B_ * T_)   // 8192

// ---------------- scratch (device globals; no runtime allocation) -------------
__device__ float g_cq[(size_t)MTOK * QLORA_];          // 8192x1536
__device__ float g_q[(size_t)MTOK * H_ * QHEAD_D_];    // 8192x3072 (assembled, roped)
__device__ float g_kvraw[(size_t)MTOK * 576];          // 8192x576
__device__ float g_ckv[(size_t)MTOK * KVLORA_];        // 8192x512 (normed)
__device__ float g_krope[(size_t)MTOK * ROPE_D_];      // 8192x64 (roped, shared across heads)
__device__ float g_kv[(size_t)MTOK * 4096];            // 8192x4096: per head [k_nope(128) | v(128)]
__device__ float g_attno[(size_t)MTOK * (H_ * V_D_)];  // 8192x2048

// ---------------- helpers ------------------------------------------------------
__device__ __forceinline__ float block_reduce_sum_256(float v) {
    __shared__ float red[8];
    int lane = threadIdx.x & 31, w = threadIdx.x >> 5;
#pragma unroll
    for (int o = 16; o; o >>= 1) v += __shfl_xor_sync(0xffffffffu, v, o);
    if (lane == 0) red[w] = v;
    __syncthreads();
    if (w == 0) {
        v = (lane < 8) ? red[lane] : 0.f;
#pragma unroll
        for (int o = 4; o; o >>= 1) v += __shfl_xor_sync(0xffffffffu, v, o);
        if (lane == 0) red[0] = v;
    }
    __syncthreads();
    return red[0];
}

__device__ __forceinline__ uint32_t f2tf32(float x) {
    uint32_t r;
    asm("cvt.rna.tf32.f32 %0, %1;" : "=r"(r) : "f"(x));
    return r;
}

__device__ __forceinline__ void mma_tf32(float* c, const uint32_t* a, const uint32_t* b) {
    asm volatile(
        "mma.sync.aligned.m16n8k8.row.col.f32.tf32.tf32.f32 "
        "{%0,%1,%2,%3},{%4,%5,%6,%7},{%8,%9},{%0,%1,%2,%3};\n"
        : "+f"(c[0]), "+f"(c[1]), "+f"(c[2]), "+f"(c[3])
        : "r"(a[0]), "r"(a[1]), "r"(a[2]), "r"(a[3]), "r"(b[0]), "r"(b[1]));
}

__device__ __forceinline__ void cp16(float* dst, const float* src, bool v) {
    uint32_t s = (uint32_t)__cvta_generic_to_shared(dst);
    int sz = v ? 16 : 0;
    asm volatile("cp.async.cg.shared.global [%0], [%1], 16, %2;\n"
                 :: "r"(s), "l"(src), "r"(sz));
}

// ---------------- tf32 tensor-core GEMM: C[m, map(n)] = sum_k A[m,k]*W[n,k] ----
// A: [M,K] row-major, W: [N,K] row-major. M % 128 == 0, K % 16 == 0.
// col = (n/group)*head_stride + n%group + col_off (plain: group=N, stride=0, off=0)
#define SA 20   // smem row stride (16 + 4 pad) -> conflict-free fragment loads

__global__ void __launch_bounds__(256, 2) tf32gemm(
    const float* __restrict__ A, const float* __restrict__ W,
    float* __restrict__ C, int M, int N, int K,
    int ldc, int group, int head_stride, int col_off)
{
    __shared__ float sbuf[2][2][128 * SA];  // [stage][A=0/B=1][row*SA + k]
    int tid = threadIdx.x;
    int bm = blockIdx.y * 128, bn = blockIdx.x * 128;
    int warp = tid >> 5, lane = tid & 31;
    int wm = warp >> 2, wn = warp & 3, grp = lane >> 2, qid = lane & 3;

    float acc[4][4][4];
#pragma unroll
    for (int mt = 0; mt < 4; mt++)
#pragma unroll
        for (int nt = 0; nt < 4; nt++)
#pragma unroll
            for (int i = 0; i < 4; i++) acc[mt][nt][i] = 0.f;

    // per-thread global-load coordinates (2 A rows + 2 B rows, 16B each)
    int ar0 = tid >> 2;             // 0..63
    int aq0 = (tid & 3) * 4;        // float offset within 16-float k chunk
    const float* A0 = A + (size_t)(bm + ar0) * K + aq0;
    const float* A1 = A + (size_t)(bm + ar0 + 64) * K + aq0;
    int n0 = bn + ar0, n1 = bn + ar0 + 64;
    bool bv0 = n0 < N, bv1 = n1 < N;
    const float* W0 = W + (size_t)(bv0 ? n0 : (N - 1)) * K + aq0;
    const float* W1 = W + (size_t)(bv1 ? n1 : (N - 1)) * K + aq0;

    int NKt = K >> 4;

    // prefetch stage 0
    {
        cp16(&sbuf[0][0][ar0 * SA + aq0], A0, true);
        cp16(&sbuf[0][0][(ar0 + 64) * SA + aq0], A1, true);
        cp16(&sbuf[0][1][ar0 * SA + aq0], W0, bv0);
        cp16(&sbuf[0][1][(ar0 + 64) * SA + aq0], W1, bv1);
        asm volatile("cp.async.commit_group;\n");
    }

    for (int kt = 0; kt < NKt; kt++) {
        int s = kt & 1;
        if (kt + 1 < NKt) {
            int koff = (kt + 1) << 4;
            cp16(&sbuf[s ^ 1][0][ar0 * SA + aq0], A0 + koff, true);
            cp16(&sbuf[s ^ 1][0][(ar0 + 64) * SA + aq0], A1 + koff, true);
            cp16(&sbuf[s ^ 1][1][ar0 * SA + aq0], W0 + koff, bv0);
            cp16(&sbuf[s ^ 1][1][(ar0 + 64) * SA + aq0], W1 + koff, bv1);
            asm volatile("cp.async.commit_group;\n");
            asm volatile("cp.async.wait_group 1;\n");
        } else {
            asm volatile("cp.async.wait_group 0;\n");
        }
        __syncthreads();

        const float* As_ = sbuf[s][0];
        const float* Bs_ = sbuf[s][1];
#pragma unroll
        for (int ks = 0; ks < 2; ks++) {
            int k0 = ks * 8;
            uint32_t bf[4][2];
#pragma unroll
            for (int nt = 0; nt < 4; nt++) {
                int nb = (wn * 32 + nt * 8 + grp) * SA + k0 + qid;
                bf[nt][0] = f2tf32(Bs_[nb]);
                bf[nt][1] = f2tf32(Bs_[nb + 4]);
            }
#pragma unroll
            for (int mt = 0; mt < 4; mt++) {
                int mb = (wm * 64 + mt * 16 + grp) * SA + k0 + qid;
                uint32_t af[4];
                af[0] = f2tf32(As_[mb]);
                af[1] = f2tf32(As_[mb + 8 * SA]);
                af[2] = f2tf32(As_[mb + 4]);
                af[3] = f2tf32(As_[mb + 8 * SA + 4]);
#pragma unroll
                for (int nt = 0; nt < 4; nt++) mma_tf32(acc[mt][nt], af, bf[nt]);
            }
        }
        __syncthreads();
    }

    // epilogue: c0/c1 -> (row, col..col+1), c2/c3 -> (row+8, ..)
    int r0 = bm + wm * 64 + grp;
    int nbase = bn + wn * 32 + qid * 2;
#pragma unroll
    for (int mt = 0; mt < 4; mt++) {
#pragma unroll
        for (int nt = 0; nt < 4; nt++) {
            int n = nbase + nt * 8;
            if (n < N) {
                int g = n / group;
                int col = g * head_stride + (n - g * group) + col_off;
                int row = r0 + mt * 16;
                *(float2*)&C[(size_t)row * ldc + col] =
                    make_float2(acc[mt][nt][0], acc[mt][nt][1]);
                *(float2*)&C[(size_t)(row + 8) * ldc + col] =
                    make_float2(acc[mt][nt][2], acc[mt][nt][3]);
            }
        }
    }
}

// ---------------- rmsnorm in place (D = 1536), w applied -----------------------
__global__ void rmsnorm_kernel(float* __restrict__ xio, const float* __restrict__ w, int D) {
    size_t row = blockIdx.x;
    float* p = xio + row * (size_t)D;
    float ss = 0.f;
    for (int i = threadIdx.x; i < D; i += 256) { float v = p[i]; ss += v * v; }
    ss = block_reduce_sum_256(ss);
    float r = rsqrtf(ss / (float)D + 1e-6f);
    for (int i = threadIdx.x; i < D; i += 256) p[i] = p[i] * r * w[i];
}

// ---------------- kv prep: rmsnorm first 512 -> g_ckv; rope last 64 -> g_krope -
__global__ void kvprep_kernel(const float* __restrict__ raw, const float* __restrict__ w,
                              const float* __restrict__ fc, const float* __restrict__ fs,
                              float* __restrict__ ckv, float* __restrict__ kr) {
    int tok = blockIdx.x;
    const float* src = raw + (size_t)tok * 576;
    float ss = 0.f;
    for (int i = threadIdx.x; i < 512; i += 256) { float v = src[i]; ss += v * v; }
    ss = block_reduce_sum_256(ss);
    float r = rsqrtf(ss / 512.f + 1e-6f);
    for (int i = threadIdx.x; i < 512; i += 256)
        ckv[(size_t)tok * 512 + i] = src[i] * r * w[i];
    if (threadIdx.x < 32) {
        int t = tok & (T_ - 1);
        int i = threadIdx.x;
        float x0 = src[512 + 2 * i], x1 = src[512 + 2 * i + 1];
        float c = fc[t * 32 + i], s = fs[t * 32 + i];
        kr[(size_t)tok * 64 + 2 * i]     = x0 * c - x1 * s;
        kr[(size_t)tok * 64 + 2 * i + 1] = x0 * s + x1 * c;
    }
}

// ---------------- rope q in place (dims 128..191 of each head) -----------------
__global__ void rope_q_kernel(float* __restrict__ q, const float* __restrict__ fc,
                              const float* __restrict__ fs) {
    int tok = blockIdx.x;
    int t = tok & (T_ - 1);
    int p = threadIdx.x;      // 512 threads: 16 heads x 32 pairs
    int h = p >> 5, i = p & 31;
    float* b = q + (size_t)tok * 3072 + h * 192 + 128;
    float x0 = b[2 * i], x1 = b[2 * i + 1];
    float c = fc[t * 32 + i], s = fs[t * 32 + i];
    b[2 * i]     = x0 * c - x1 * s;
    b[2 * i + 1] = x0 * s + x1 * c;
}

// ---------------- flash attention (fp32, causal) -------------------------------
// Br=Bc=64, 256 threads (16x16). S microtile 4x4/thread (cols tx + j*16),
// O microtile 4x8/thread. All smem streamed via float4 (K stored row-major).
#define QS 196    // 192 + 4 pad
#define KSB 196
#define VSB 128
#define PSB 68    // 64 + 4 pad
#define ATT_SMEM_FLOATS (64 * QS + 64 * KSB + 64 * VSB + 64 * PSB)
#define ATT_SMEM_BYTES (ATT_SMEM_FLOATS * 4)

__global__ void __launch_bounds__(256) attn_kernel(
    const float* __restrict__ q, const float* __restrict__ kv,
    const float* __restrict__ krope, float* __restrict__ out)
{
    extern __shared__ float sm[];
    float* sQ = sm;                 // [64][QS]
    float* sK = sQ + 64 * QS;       // [64][KSB]  (nope 0..127 | rope 128..191)
    float* sV = sK + 64 * KSB;      // [64][VSB]
    float* sP = sV + 64 * VSB;      // [64][PSB]

    int b = blockIdx.z, h = blockIdx.y, qt = blockIdx.x;
    int tid = threadIdx.x;
    int tx = tid & 15, ty = tid >> 4;
    int t0 = b * T_ + qt * 64;

    // load Q tile [64 x 192] as float4
    for (int idx = tid; idx < 64 * 48; idx += 256) {
        int r = idx / 48, f = idx - r * 48;
        *(float4*)&sQ[r * QS + f * 4] =
            *(const float4*)&q[(size_t)(t0 + r) * 3072 + h * 192 + f * 4];
    }

    float m[4], l[4], acc[4][8];
#pragma unroll
    for (int i = 0; i < 4; i++) {
        m[i] = -1e30f; l[i] = 0.f;
#pragma unroll
        for (int j = 0; j < 8; j++) acc[i][j] = 0.f;
    }
    const float scale = 0.07216878364870323f;  // 1/sqrt(192)

    for (int jt = 0; jt <= qt; jt++) {
        int kb = b * T_ + jt * 64;
        __syncthreads();   // previous iter done with sK/sV/sP; also orders sQ writes
        // load K nope + V (row-major, direct float4 copies)
        for (int idx = tid; idx < 64 * 32; idx += 256) {
            int c = idx >> 5, f = idx & 31;
            const float4* src = (const float4*)&kv[(size_t)(kb + c) * 4096 + h * 256];
            *(float4*)&sK[c * KSB + f * 4] = src[f];
            *(float4*)&sV[c * VSB + f * 4] = src[32 + f];
        }
        // K rope (shared across heads) appended at cols 128..191
        for (int idx = tid; idx < 64 * 16; idx += 256) {
            int c = idx >> 4, f = idx & 15;
            *(float4*)&sK[c * KSB + 128 + f * 4] =
                *(const float4*)&krope[(size_t)(kb + c) * 64 + f * 4];
        }
        __syncthreads();

        // S = Q K^T : rows ty*4+i, cols tx + j*16
        float s[4][4];
#pragma unroll
        for (int i = 0; i < 4; i++)
#pragma unroll
            for (int j = 0; j < 4; j++) s[i][j] = 0.f;
        for (int d0 = 0; d0 < 192; d0 += 4) {
            float4 qv[4], kf[4];
#pragma unroll
            for (int i = 0; i < 4; i++) qv[i] = *(const float4*)&sQ[(ty * 4 + i) * QS + d0];
#pragma unroll
            for (int j = 0; j < 4; j++) kf[j] = *(const float4*)&sK[(tx + j * 16) * KSB + d0];
#pragma unroll
            for (int i = 0; i < 4; i++)
#pragma unroll
                for (int j = 0; j < 4; j++) {
                    s[i][j] = fmaf(qv[i].x, kf[j].x, s[i][j]);
                    s[i][j] = fmaf(qv[i].y, kf[j].y, s[i][j]);
                    s[i][j] = fmaf(qv[i].z, kf[j].z, s[i][j]);
                    s[i][j] = fmaf(qv[i].w, kf[j].w, s[i][j]);
                }
        }
        // scale + causal mask (diagonal tile only)
        bool diag = (jt == qt);
#pragma unroll
        for (int i = 0; i < 4; i++)
#pragma unroll
            for (int j = 0; j < 4; j++) {
                s[i][j] *= scale;
                if (diag && (tx + j * 16) > (ty * 4 + i)) s[i][j] = -1e30f;
            }
        // online softmax update
#pragma unroll
        for (int i = 0; i < 4; i++) {
            float v = fmaxf(fmaxf(s[i][0], s[i][1]), fmaxf(s[i][2], s[i][3]));
#pragma unroll
            for (int o = 8; o; o >>= 1) v = fmaxf(v, __shfl_xor_sync(0xffffffffu, v, o));
            float mn = fmaxf(m[i], v);
            float alpha = __expf(m[i] - mn);
            m[i] = mn;
            float sum = 0.f;
#pragma unroll
            for (int j = 0; j < 4; j++) {
                float p = __expf(s[i][j] - mn);
                sP[(ty * 4 + i) * PSB + tx + j * 16] = p;
                sum += p;
            }
#pragma unroll
            for (int o = 8; o; o >>= 1) sum += __shfl_xor_sync(0xffffffffu, sum, o);
            l[i] = l[i] * alpha + sum;
#pragma unroll
            for (int j = 0; j < 8; j++) acc[i][j] *= alpha;
        }
        __syncthreads();
        // O += P V   (4x8 per thread)
        for (int c = 0; c < 64; c++) {
            float4 v0 = *(const float4*)&sV[c * VSB + tx * 8];
            float4 v1 = *(const float4*)&sV[c * VSB + tx * 8 + 4];
#pragma unroll
            for (int i = 0; i < 4; i++) {
                float p = sP[(ty * 4 + i) * PSB + c];
                acc[i][0] = fmaf(p, v0.x, acc[i][0]);
                acc[i][1] = fmaf(p, v0.y, acc[i][1]);
                acc[i][2] = fmaf(p, v0.z, acc[i][2]);
                acc[i][3] = fmaf(p, v0.w, acc[i][3]);
                acc[i][4] = fmaf(p, v1.x, acc[i][4]);
                acc[i][5] = fmaf(p, v1.y, acc[i][5]);
                acc[i][6] = fmaf(p, v1.z, acc[i][6]);
                acc[i][7] = fmaf(p, v1.w, acc[i][7]);
            }
        }
    }

    // write normalized output: [tok][h*128 + dv]
#pragma unroll
    for (int i = 0; i < 4; i++) {
        float inv = 1.f / l[i];
        size_t base = (size_t)(t0 + ty * 4 + i) * 2048 + h * 128 + tx * 8;
#pragma unroll
        for (int j = 0; j < 8; j++) out[base + j] = acc[i][j] * inv;
    }
}

// ---------------- launch -------------------------------------------------------
extern "C" void kernel_launch(void* const* d_in, const int* in_sizes, int n_in,
                              void* d_out, int out_size) {
    const float* x           = (const float*)d_in[0];
    const float* fc          = (const float*)d_in[1];
    const float* fs          = (const float*)d_in[2];
    // d_in[3] = mask (causal, implemented directly)
    const float* q_down_w    = (const float*)d_in[4];
    const float* q_norm_w    = (const float*)d_in[5];
    const float* q_up_nope_w = (const float*)d_in[6];
    const float* q_up_rope_w = (const float*)d_in[7];
    const float* kv_down_w   = (const float*)d_in[8];
    const float* kv_norm_w   = (const float*)d_in[9];
    const float* kv_up_w     = (const float*)d_in[10];
    const float* wo_w        = (const float*)d_in[11];
    float* out = (float*)d_out;

    float *cq, *qbuf, *kvraw, *ckv, *krope, *kvbuf, *attno;
    cudaGetSymbolAddress((void**)&cq,    g_cq);
    cudaGetSymbolAddress((void**)&qbuf,  g_q);
    cudaGetSymbolAddress((void**)&kvraw, g_kvraw);
    cudaGetSymbolAddress((void**)&ckv,   g_ckv);
    cudaGetSymbolAddress((void**)&krope, g_krope);
    cudaGetSymbolAddress((void**)&kvbuf, g_kv);
    cudaGetSymbolAddress((void**)&attno, g_attno);

    dim3 blk(256);
    // q_down: [8192,2048] x [1536,2048] -> g_cq
    tf32gemm<<<dim3(QLORA_ / 128, MTOK / 128), blk>>>(x, q_down_w, cq,
        MTOK, QLORA_, DIM_, QLORA_, QLORA_, 0, 0);
    rmsnorm_kernel<<<MTOK, 256>>>(cq, q_norm_w, QLORA_);

    // kv_down: N=576
    tf32gemm<<<dim3(5, MTOK / 128), blk>>>(x, kv_down_w, kvraw,
        MTOK, 576, DIM_, 576, 576, 0, 0);
    kvprep_kernel<<<MTOK, 256>>>(kvraw, kv_norm_w, fc, fs, ckv, krope);

    // q_up_nope -> g_q[tok, h*192 + 0..127]
    tf32gemm<<<dim3(2048 / 128, MTOK / 128), blk>>>(cq, q_up_nope_w, qbuf,
        MTOK, 2048, QLORA_, 3072, 128, 192, 0);
    // q_up_rope -> g_q[tok, h*192 + 128..191]
    tf32gemm<<<dim3(1024 / 128, MTOK / 128), blk>>>(cq, q_up_rope_w, qbuf,
        MTOK, 1024, QLORA_, 3072, 64, 192, 128);
    rope_q_kernel<<<MTOK, 512>>>(qbuf, fc, fs);

    // kv_up: [8192,512] x [4096,512] -> g_kv
    tf32gemm<<<dim3(4096 / 128, MTOK / 128), blk>>>(ckv, kv_up_w, kvbuf,
        MTOK, 4096, KVLORA_, 4096, 4096, 0, 0);

    // attention
    cudaFuncSetAttribute(attn_kernel, cudaFuncAttributeMaxDynamicSharedMemorySize, ATT_SMEM_BYTES);
    attn_kernel<<<dim3(T_ / 64, H_, B_), 256, ATT_SMEM_BYTES>>>(qbuf, kvbuf, krope, attno);

    // wo: [8192,2048] x [2048,2048] -> out
    tf32gemm<<<dim3(2048 / 128, MTOK / 128), blk>>>(attno, wo_w, out,
        MTOK, 2048, 2048, 2048, 2048, 0, 0);
}

// round 3
// speedup vs baseline: 3.2401x; 1.5473x over previous
#include <cuda_runtime.h>
#include <cuda_bf16.h>
#include <cstdint>

// Problem constants
#define B_ 4
#define T_ 2048
#define DIM_ 2048
#define H_ 16
#define QLORA_ 1536
#define KVLORA_ 512
#define ROPE_D_ 64
#define NOPE_D_ 128
#define V_D_ 128
#define QHEAD_D_ 192
#define MTOK (B_ * T_)   // 8192

// ---------------- scratch (device globals; no runtime allocation) -------------
__device__ float g_cq[(size_t)MTOK * QLORA_];
__device__ float g_q[(size_t)MTOK * H_ * QHEAD_D_];
__device__ float g_kvraw[(size_t)MTOK * 576];
__device__ float g_ckv[(size_t)MTOK * KVLORA_];
__device__ float g_krope[(size_t)MTOK * ROPE_D_];
__device__ float g_kv[(size_t)MTOK * 4096];
__device__ float g_attno[(size_t)MTOK * (H_ * V_D_)];

// ---------------- helpers ------------------------------------------------------
__device__ __forceinline__ float block_reduce_sum_256(float v) {
    __shared__ float red[8];
    int lane = threadIdx.x & 31, w = threadIdx.x >> 5;
#pragma unroll
    for (int o = 16; o; o >>= 1) v += __shfl_xor_sync(0xffffffffu, v, o);
    if (lane == 0) red[w] = v;
    __syncthreads();
    if (w == 0) {
        v = (lane < 8) ? red[lane] : 0.f;
#pragma unroll
        for (int o = 4; o; o >>= 1) v += __shfl_xor_sync(0xffffffffu, v, o);
        if (lane == 0) red[0] = v;
    }
    __syncthreads();
    return red[0];
}

__device__ __forceinline__ uint32_t f2tf32(float x) {
    uint32_t r;
    asm("cvt.rna.tf32.f32 %0, %1;" : "=r"(r) : "f"(x));
    return r;
}
__device__ __forceinline__ float tf32rf(float x) {
    return __uint_as_float(f2tf32(x));
}
__device__ __forceinline__ float ex2(float x) {
    float r;
    asm("ex2.approx.ftz.f32 %0, %1;" : "=f"(r) : "f"(x));
    return r;
}
__device__ __forceinline__ uint32_t FU(float x) { return __float_as_uint(x); }

__device__ __forceinline__ void mma_tf32(float* c, const uint32_t* a, const uint32_t* b) {
    asm volatile(
        "mma.sync.aligned.m16n8k8.row.col.f32.tf32.tf32.f32 "
        "{%0,%1,%2,%3},{%4,%5,%6,%7},{%8,%9},{%0,%1,%2,%3};\n"
        : "+f"(c[0]), "+f"(c[1]), "+f"(c[2]), "+f"(c[3])
        : "r"(a[0]), "r"(a[1]), "r"(a[2]), "r"(a[3]), "r"(b[0]), "r"(b[1]));
}

__device__ __forceinline__ void cp16(float* dst, const float* src, bool v) {
    uint32_t s = (uint32_t)__cvta_generic_to_shared(dst);
    int sz = v ? 16 : 0;
    asm volatile("cp.async.cg.shared.global [%0], [%1], 16, %2;\n"
                 :: "r"(s), "l"(src), "r"(sz));
}

// ---------------- tf32 tensor-core GEMM (unchanged from round 2) ---------------
#define SA 20

__global__ void __launch_bounds__(256, 2) tf32gemm(
    const float* __restrict__ A, const float* __restrict__ W,
    float* __restrict__ C, int M, int N, int K,
    int ldc, int group, int head_stride, int col_off)
{
    __shared__ float sbuf[2][2][128 * SA];
    int tid = threadIdx.x;
    int bm = blockIdx.y * 128, bn = blockIdx.x * 128;
    int warp = tid >> 5, lane = tid & 31;
    int wm = warp >> 2, wn = warp & 3, grp = lane >> 2, qid = lane & 3;

    float acc[4][4][4];
#pragma unroll
    for (int mt = 0; mt < 4; mt++)
#pragma unroll
        for (int nt = 0; nt < 4; nt++)
#pragma unroll
            for (int i = 0; i < 4; i++) acc[mt][nt][i] = 0.f;

    int ar0 = tid >> 2;
    int aq0 = (tid & 3) * 4;
    const float* A0 = A + (size_t)(bm + ar0) * K + aq0;
    const float* A1 = A + (size_t)(bm + ar0 + 64) * K + aq0;
    int n0 = bn + ar0, n1 = bn + ar0 + 64;
    bool bv0 = n0 < N, bv1 = n1 < N;
    const float* W0 = W + (size_t)(bv0 ? n0 : (N - 1)) * K + aq0;
    const float* W1 = W + (size_t)(bv1 ? n1 : (N - 1)) * K + aq0;

    int NKt = K >> 4;
    {
        cp16(&sbuf[0][0][ar0 * SA + aq0], A0, true);
        cp16(&sbuf[0][0][(ar0 + 64) * SA + aq0], A1, true);
        cp16(&sbuf[0][1][ar0 * SA + aq0], W0, bv0);
        cp16(&sbuf[0][1][(ar0 + 64) * SA + aq0], W1, bv1);
        asm volatile("cp.async.commit_group;\n");
    }

    for (int kt = 0; kt < NKt; kt++) {
        int s = kt & 1;
        if (kt + 1 < NKt) {
            int koff = (kt + 1) << 4;
            cp16(&sbuf[s ^ 1][0][ar0 * SA + aq0], A0 + koff, true);
            cp16(&sbuf[s ^ 1][0][(ar0 + 64) * SA + aq0], A1 + koff, true);
            cp16(&sbuf[s ^ 1][1][ar0 * SA + aq0], W0 + koff, bv0);
            cp16(&sbuf[s ^ 1][1][(ar0 + 64) * SA + aq0], W1 + koff, bv1);
            asm volatile("cp.async.commit_group;\n");
            asm volatile("cp.async.wait_group 1;\n");
        } else {
            asm volatile("cp.async.wait_group 0;\n");
        }
        __syncthreads();

        const float* As_ = sbuf[s][0];
        const float* Bs_ = sbuf[s][1];
#pragma unroll
        for (int ks = 0; ks < 2; ks++) {
            int k0 = ks * 8;
            uint32_t bf[4][2];
#pragma unroll
            for (int nt = 0; nt < 4; nt++) {
                int nb = (wn * 32 + nt * 8 + grp) * SA + k0 + qid;
                bf[nt][0] = f2tf32(Bs_[nb]);
                bf[nt][1] = f2tf32(Bs_[nb + 4]);
            }
#pragma unroll
            for (int mt = 0; mt < 4; mt++) {
                int mb = (wm * 64 + mt * 16 + grp) * SA + k0 + qid;
                uint32_t af[4];
                af[0] = f2tf32(As_[mb]);
                af[1] = f2tf32(As_[mb + 8 * SA]);
                af[2] = f2tf32(As_[mb + 4]);
                af[3] = f2tf32(As_[mb + 8 * SA + 4]);
#pragma unroll
                for (int nt = 0; nt < 4; nt++) mma_tf32(acc[mt][nt], af, bf[nt]);
            }
        }
        __syncthreads();
    }

    int r0 = bm + wm * 64 + grp;
    int nbase = bn + wn * 32 + qid * 2;
#pragma unroll
    for (int mt = 0; mt < 4; mt++) {
#pragma unroll
        for (int nt = 0; nt < 4; nt++) {
            int n = nbase + nt * 8;
            if (n < N) {
                int g = n / group;
                int col = g * head_stride + (n - g * group) + col_off;
                int row = r0 + mt * 16;
                *(float2*)&C[(size_t)row * ldc + col] =
                    make_float2(acc[mt][nt][0], acc[mt][nt][1]);
                *(float2*)&C[(size_t)(row + 8) * ldc + col] =
                    make_float2(acc[mt][nt][2], acc[mt][nt][3]);
            }
        }
    }
}

// ---------------- rmsnorm / kvprep / rope --------------------------------------
__global__ void rmsnorm_kernel(float* __restrict__ xio, const float* __restrict__ w, int D) {
    size_t row = blockIdx.x;
    float* p = xio + row * (size_t)D;
    float ss = 0.f;
    for (int i = threadIdx.x; i < D; i += 256) { float v = p[i]; ss += v * v; }
    ss = block_reduce_sum_256(ss);
    float r = rsqrtf(ss / (float)D + 1e-6f);
    for (int i = threadIdx.x; i < D; i += 256) p[i] = p[i] * r * w[i];
}

__global__ void kvprep_kernel(const float* __restrict__ raw, const float* __restrict__ w,
                              const float* __restrict__ fc, const float* __restrict__ fs,
                              float* __restrict__ ckv, float* __restrict__ kr) {
    int tok = blockIdx.x;
    const float* src = raw + (size_t)tok * 576;
    float ss = 0.f;
    for (int i = threadIdx.x; i < 512; i += 256) { float v = src[i]; ss += v * v; }
    ss = block_reduce_sum_256(ss);
    float r = rsqrtf(ss / 512.f + 1e-6f);
    for (int i = threadIdx.x; i < 512; i += 256)
        ckv[(size_t)tok * 512 + i] = src[i] * r * w[i];
    if (threadIdx.x < 32) {
        int t = tok & (T_ - 1);
        int i = threadIdx.x;
        float x0 = src[512 + 2 * i], x1 = src[512 + 2 * i + 1];
        float c = fc[t * 32 + i], s = fs[t * 32 + i];
        kr[(size_t)tok * 64 + 2 * i]     = x0 * c - x1 * s;
        kr[(size_t)tok * 64 + 2 * i + 1] = x0 * s + x1 * c;
    }
}

__global__ void rope_q_kernel(float* __restrict__ q, const float* __restrict__ fc,
                              const float* __restrict__ fs) {
    int tok = blockIdx.x;
    int t = tok & (T_ - 1);
    int p = threadIdx.x;
    int h = p >> 5, i = p & 31;
    float* b = q + (size_t)tok * 3072 + h * 192 + 128;
    float x0 = b[2 * i], x1 = b[2 * i + 1];
    float c = fc[t * 32 + i], s = fs[t * 32 + i];
    b[2 * i]     = x0 * c - x1 * s;
    b[2 * i + 1] = x0 * s + x1 * c;
}

// ---------------- tensor-core flash attention (tf32, causal) -------------------
// Br=Bc=64, 256 threads = 8 warps (4 row-groups x 2 col-groups).
// S via mma tf32 (Q pre-scaled by scale*log2e, operands rna-rounded at store).
// Softmax in log2 domain; P rounded to tf32 in smem; O += P V via mma tf32.
#define AQS 196   // mod 32 = 4 -> conflict-free A/B fragment loads
#define AKS 196
#define AVS 136   // mod 32 = 8 -> conflict-free B fragment loads
#define APS 68    // mod 32 = 4
#define ASM_FLOATS (64*AQS + 64*AKS + 64*AVS + 64*APS + 128 + 128)
#define ASM_BYTES (ASM_FLOATS * 4)

__global__ void __launch_bounds__(256) attn_mma_kernel(
    const float* __restrict__ q, const float* __restrict__ kv,
    const float* __restrict__ krope, float* __restrict__ out)
{
    extern __shared__ float sm[];
    float* sQ  = sm;                  // [64][AQS]  scaled+rounded
    float* sK  = sQ + 64 * AQS;       // [64][AKS]  nope 0..127 | rope 128..191
    float* sV  = sK + 64 * AKS;       // [64][AVS]
    float* sP  = sV + 64 * AVS;       // [64][APS]
    float* sRM = sP + 64 * APS;       // [64][2] row-max partials
    float* sRL = sRM + 128;           // [64][2] row-l partials

    int b = blockIdx.z, h = blockIdx.y, qt = blockIdx.x;
    int tid = threadIdx.x;
    int warp = tid >> 5, lane = tid & 31;
    int wm = warp >> 1, wn = warp & 1;
    int grp = lane >> 2, qid = lane & 3;
    int t0 = b * T_ + qt * 64;
    int r0 = wm * 16 + grp, r1 = r0 + 8;

    const float qsc = 0.07216878364870323f * 1.4426950408889634f; // scale*log2e

    // load Q tile [64 x 192], fold scale+log2e, round to tf32
    for (int idx = tid; idx < 64 * 48; idx += 256) {
        int r = idx / 48, f = (idx - r * 48) * 4;
        float4 v = *(const float4*)&q[(size_t)(t0 + r) * 3072 + h * 192 + f];
        sQ[r * AQS + f + 0] = tf32rf(v.x * qsc);
        sQ[r * AQS + f + 1] = tf32rf(v.y * qsc);
        sQ[r * AQS + f + 2] = tf32rf(v.z * qsc);
        sQ[r * AQS + f + 3] = tf32rf(v.w * qsc);
    }

    float m0 = -1e30f, m1 = -1e30f, l0 = 0.f, l1 = 0.f;
    float accO[8][4];
#pragma unroll
    for (int nt = 0; nt < 8; nt++)
#pragma unroll
        for (int i = 0; i < 4; i++) accO[nt][i] = 0.f;

    for (int jt = 0; jt <= qt; jt++) {
        int kb = b * T_ + jt * 64;
        __syncthreads();   // prev iter done with sK/sV/sP (+ first iter: sQ writes)
        // K nope + V, rounded
        for (int idx = tid; idx < 64 * 32; idx += 256) {
            int c = idx >> 5, f = idx & 31;
            const float4* src = (const float4*)&kv[(size_t)(kb + c) * 4096 + h * 256];
            float4 kk = src[f], vv = src[32 + f];
            float* kd = &sK[c * AKS + f * 4];
            kd[0] = tf32rf(kk.x); kd[1] = tf32rf(kk.y); kd[2] = tf32rf(kk.z); kd[3] = tf32rf(kk.w);
            float* vd = &sV[c * AVS + f * 4];
            vd[0] = tf32rf(vv.x); vd[1] = tf32rf(vv.y); vd[2] = tf32rf(vv.z); vd[3] = tf32rf(vv.w);
        }
        // K rope cols 128..191
        for (int idx = tid; idx < 64 * 16; idx += 256) {
            int c = idx >> 4, f = idx & 15;
            float4 kk = *(const float4*)&krope[(size_t)(kb + c) * 64 + f * 4];
            float* kd = &sK[c * AKS + 128 + f * 4];
            kd[0] = tf32rf(kk.x); kd[1] = tf32rf(kk.y); kd[2] = tf32rf(kk.z); kd[3] = tf32rf(kk.w);
        }
        __syncthreads();

        // S = Q K^T (warp tile 16x32)
        float sfr[4][4];
#pragma unroll
        for (int nt = 0; nt < 4; nt++)
#pragma unroll
            for (int i = 0; i < 4; i++) sfr[nt][i] = 0.f;
#pragma unroll 4
        for (int ks = 0; ks < 24; ks++) {
            int k0 = ks * 8;
            uint32_t af[4];
            af[0] = FU(sQ[r0 * AQS + k0 + qid]);
            af[1] = FU(sQ[r1 * AQS + k0 + qid]);
            af[2] = FU(sQ[r0 * AQS + k0 + qid + 4]);
            af[3] = FU(sQ[r1 * AQS + k0 + qid + 4]);
#pragma unroll
            for (int nt = 0; nt < 4; nt++) {
                int n = wn * 32 + nt * 8 + grp;
                uint32_t bf[2] = { FU(sK[n * AKS + k0 + qid]),
                                   FU(sK[n * AKS + k0 + qid + 4]) };
                mma_tf32(sfr[nt], af, bf);
            }
        }

        // causal mask on diagonal tile
        if (jt == qt) {
#pragma unroll
            for (int nt = 0; nt < 4; nt++) {
                int c0 = wn * 32 + nt * 8 + 2 * qid;
                if (c0 > r0)     sfr[nt][0] = -1e30f;
                if (c0 + 1 > r0) sfr[nt][1] = -1e30f;
                if (c0 > r1)     sfr[nt][2] = -1e30f;
                if (c0 + 1 > r1) sfr[nt][3] = -1e30f;
            }
        }

        // row max (warp-partial over 32 cols)
        float mx0 = -1e30f, mx1 = -1e30f;
#pragma unroll
        for (int nt = 0; nt < 4; nt++) {
            mx0 = fmaxf(mx0, fmaxf(sfr[nt][0], sfr[nt][1]));
            mx1 = fmaxf(mx1, fmaxf(sfr[nt][2], sfr[nt][3]));
        }
        mx0 = fmaxf(mx0, __shfl_xor_sync(0xffffffffu, mx0, 1));
        mx0 = fmaxf(mx0, __shfl_xor_sync(0xffffffffu, mx0, 2));
        mx1 = fmaxf(mx1, __shfl_xor_sync(0xffffffffu, mx1, 1));
        mx1 = fmaxf(mx1, __shfl_xor_sync(0xffffffffu, mx1, 2));
        if (qid == 0) { sRM[r0 * 2 + wn] = mx0; sRM[r1 * 2 + wn] = mx1; }
        __syncthreads();
        float mn0 = fmaxf(m0, fmaxf(sRM[r0 * 2], sRM[r0 * 2 + 1]));
        float mn1 = fmaxf(m1, fmaxf(sRM[r1 * 2], sRM[r1 * 2 + 1]));
        float al0 = ex2(m0 - mn0), al1 = ex2(m1 - mn1);
        m0 = mn0; m1 = mn1;

        // exp (log2 domain), store rounded P, row sums
        float sum0 = 0.f, sum1 = 0.f;
#pragma unroll
        for (int nt = 0; nt < 4; nt++) {
            int c0 = wn * 32 + nt * 8 + 2 * qid;
            float p00 = ex2(sfr[nt][0] - mn0), p01 = ex2(sfr[nt][1] - mn0);
            float p10 = ex2(sfr[nt][2] - mn1), p11 = ex2(sfr[nt][3] - mn1);
            sum0 += p00 + p01;
            sum1 += p10 + p11;
            *(float2*)&sP[r0 * APS + c0] = make_float2(tf32rf(p00), tf32rf(p01));
            *(float2*)&sP[r1 * APS + c0] = make_float2(tf32rf(p10), tf32rf(p11));
        }
        sum0 += __shfl_xor_sync(0xffffffffu, sum0, 1);
        sum0 += __shfl_xor_sync(0xffffffffu, sum0, 2);
        sum1 += __shfl_xor_sync(0xffffffffu, sum1, 1);
        sum1 += __shfl_xor_sync(0xffffffffu, sum1, 2);
        l0 = l0 * al0 + sum0;
        l1 = l1 * al1 + sum1;

        // rescale O
#pragma unroll
        for (int nt = 0; nt < 8; nt++) {
            accO[nt][0] *= al0; accO[nt][1] *= al0;
            accO[nt][2] *= al1; accO[nt][3] *= al1;
        }
        __syncthreads();   // P complete (both wn warps)

        // O += P V (warp tile 16x64)
#pragma unroll
        for (int ks = 0; ks < 8; ks++) {
            int k0 = ks * 8;
            uint32_t pa[4];
            pa[0] = FU(sP[r0 * APS + k0 + qid]);
            pa[1] = FU(sP[r1 * APS + k0 + qid]);
            pa[2] = FU(sP[r0 * APS + k0 + qid + 4]);
            pa[3] = FU(sP[r1 * APS + k0 + qid + 4]);
#pragma unroll
            for (int nt = 0; nt < 8; nt++) {
                int vb = wn * 64 + nt * 8 + grp;
                uint32_t bf[2] = { FU(sV[(k0 + qid) * AVS + vb]),
                                   FU(sV[(k0 + qid + 4) * AVS + vb]) };
                mma_tf32(accO[nt], pa, bf);
            }
        }
    }

    // merge l across wn, normalize, write out
    if (qid == 0) { sRL[r0 * 2 + wn] = l0; sRL[r1 * 2 + wn] = l1; }
    __syncthreads();
    float inv0 = 1.f / (sRL[r0 * 2] + sRL[r0 * 2 + 1]);
    float inv1 = 1.f / (sRL[r1 * 2] + sRL[r1 * 2 + 1]);
#pragma unroll
    for (int nt = 0; nt < 8; nt++) {
        int col = h * 128 + wn * 64 + nt * 8 + 2 * qid;
        *(float2*)&out[(size_t)(t0 + r0) * 2048 + col] =
            make_float2(accO[nt][0] * inv0, accO[nt][1] * inv0);
        *(float2*)&out[(size_t)(t0 + r1) * 2048 + col] =
            make_float2(accO[nt][2] * inv1, accO[nt][3] * inv1);
    }
}

// ---------------- launch -------------------------------------------------------
extern "C" void kernel_launch(void* const* d_in, const int* in_sizes, int n_in,
                              void* d_out, int out_size) {
    const float* x           = (const float*)d_in[0];
    const float* fc          = (const float*)d_in[1];
    const float* fs          = (const float*)d_in[2];
    const float* q_down_w    = (const float*)d_in[4];
    const float* q_norm_w    = (const float*)d_in[5];
    const float* q_up_nope_w = (const float*)d_in[6];
    const float* q_up_rope_w = (const float*)d_in[7];
    const float* kv_down_w   = (const float*)d_in[8];
    const float* kv_norm_w   = (const float*)d_in[9];
    const float* kv_up_w     = (const float*)d_in[10];
    const float* wo_w        = (const float*)d_in[11];
    float* out = (float*)d_out;

    float *cq, *qbuf, *kvraw, *ckv, *krope, *kvbuf, *attno;
    cudaGetSymbolAddress((void**)&cq,    g_cq);
    cudaGetSymbolAddress((void**)&qbuf,  g_q);
    cudaGetSymbolAddress((void**)&kvraw, g_kvraw);
    cudaGetSymbolAddress((void**)&ckv,   g_ckv);
    cudaGetSymbolAddress((void**)&krope, g_krope);
    cudaGetSymbolAddress((void**)&kvbuf, g_kv);
    cudaGetSymbolAddress((void**)&attno, g_attno);

    dim3 blk(256);
    tf32gemm<<<dim3(QLORA_ / 128, MTOK / 128), blk>>>(x, q_down_w, cq,
        MTOK, QLORA_, DIM_, QLORA_, QLORA_, 0, 0);
    rmsnorm_kernel<<<MTOK, 256>>>(cq, q_norm_w, QLORA_);

    tf32gemm<<<dim3(5, MTOK / 128), blk>>>(x, kv_down_w, kvraw,
        MTOK, 576, DIM_, 576, 576, 0, 0);
    kvprep_kernel<<<MTOK, 256>>>(kvraw, kv_norm_w, fc, fs, ckv, krope);

    tf32gemm<<<dim3(2048 / 128, MTOK / 128), blk>>>(cq, q_up_nope_w, qbuf,
        MTOK, 2048, QLORA_, 3072, 128, 192, 0);
    tf32gemm<<<dim3(1024 / 128, MTOK / 128), blk>>>(cq, q_up_rope_w, qbuf,
        MTOK, 1024, QLORA_, 3072, 64, 192, 128);
    rope_q_kernel<<<MTOK, 512>>>(qbuf, fc, fs);

    tf32gemm<<<dim3(4096 / 128, MTOK / 128), blk>>>(ckv, kv_up_w, kvbuf,
        MTOK, 4096, KVLORA_, 4096, 4096, 0, 0);

    cudaFuncSetAttribute(attn_mma_kernel, cudaFuncAttributeMaxDynamicSharedMemorySize, ASM_BYTES);
    attn_mma_kernel<<<dim3(T_ / 64, H_, B_), 256, ASM_BYTES>>>(qbuf, kvbuf, krope, attno);

    tf32gemm<<<dim3(2048 / 128, MTOK / 128), blk>>>(attno, wo_w, out,
        MTOK, 2048, 2048, 2048, 2048, 0, 0);
}

// round 4
// speedup vs baseline: 3.2513x; 1.0034x over previous
#include <cuda_runtime.h>
#include <cuda_bf16.h>
#include <cstdint>

// Problem constants
#define B_ 4
#define T_ 2048
#define DIM_ 2048
#define H_ 16
#define QLORA_ 1536
#define KVLORA_ 512
#define ROPE_D_ 64
#define NOPE_D_ 128
#define V_D_ 128
#define QHEAD_D_ 192
#define MTOK (B_ * T_)   // 8192

// ---------------- scratch (device globals; no runtime allocation) -------------
__device__ float g_cq[(size_t)MTOK * QLORA_];
__device__ float g_q[(size_t)MTOK * H_ * QHEAD_D_];
__device__ float g_kvraw[(size_t)MTOK * 576];
__device__ float g_ckv[(size_t)MTOK * KVLORA_];
__device__ float g_krope[(size_t)MTOK * ROPE_D_];
__device__ float g_kv[(size_t)MTOK * 4096];
__device__ float g_attno[(size_t)MTOK * (H_ * V_D_)];
// pre-rounded (tf32) operands
__device__ float g_xr[(size_t)MTOK * DIM_];                 // 8192x2048
__device__ float g_w_qdown[(size_t)QLORA_ * DIM_];          // 1536x2048
__device__ float g_w_kvdown[(size_t)576 * DIM_];            // 576x2048
__device__ float g_w_qup[(size_t)3072 * QLORA_];            // 3072x1536 (head-interleaved)
__device__ float g_w_kvup[(size_t)4096 * KVLORA_];          // 4096x512
__device__ float g_w_wo[(size_t)DIM_ * 2048];               // 2048x2048

// ---------------- helpers ------------------------------------------------------
__device__ __forceinline__ float block_reduce_sum_256(float v) {
    __shared__ float red[8];
    int lane = threadIdx.x & 31, w = threadIdx.x >> 5;
#pragma unroll
    for (int o = 16; o; o >>= 1) v += __shfl_xor_sync(0xffffffffu, v, o);
    if (lane == 0) red[w] = v;
    __syncthreads();
    if (w == 0) {
        v = (lane < 8) ? red[lane] : 0.f;
#pragma unroll
        for (int o = 4; o; o >>= 1) v += __shfl_xor_sync(0xffffffffu, v, o);
        if (lane == 0) red[0] = v;
    }
    __syncthreads();
    return red[0];
}

__device__ __forceinline__ uint32_t f2tf32(float x) {
    uint32_t r;
    asm("cvt.rna.tf32.f32 %0, %1;" : "=r"(r) : "f"(x));
    return r;
}
__device__ __forceinline__ float tf32rf(float x) {
    return __uint_as_float(f2tf32(x));
}
__device__ __forceinline__ float ex2(float x) {
    float r;
    asm("ex2.approx.ftz.f32 %0, %1;" : "=f"(r) : "f"(x));
    return r;
}
__device__ __forceinline__ uint32_t FU(float x) { return __float_as_uint(x); }

__device__ __forceinline__ void mma_tf32(float* c, const uint32_t* a, const uint32_t* b) {
    asm volatile(
        "mma.sync.aligned.m16n8k8.row.col.f32.tf32.tf32.f32 "
        "{%0,%1,%2,%3},{%4,%5,%6,%7},{%8,%9},{%0,%1,%2,%3};\n"
        : "+f"(c[0]), "+f"(c[1]), "+f"(c[2]), "+f"(c[3])
        : "r"(a[0]), "r"(a[1]), "r"(a[2]), "r"(a[3]), "r"(b[0]), "r"(b[1]));
}

__device__ __forceinline__ void cp16(float* dst, const float* src, bool v) {
    uint32_t s = (uint32_t)__cvta_generic_to_shared(dst);
    int sz = v ? 16 : 0;
    asm volatile("cp.async.cg.shared.global [%0], [%1], 16, %2;\n"
                 :: "r"(s), "l"(src), "r"(sz));
}

// ---------------- rounding copy kernels ----------------------------------------
__global__ void round_copy(const float* __restrict__ src, float* __restrict__ dst, int n4) {
    int i = blockIdx.x * blockDim.x + threadIdx.x;
    if (i < n4) {
        float4 v = ((const float4*)src)[i];
        v.x = tf32rf(v.x); v.y = tf32rf(v.y); v.z = tf32rf(v.z); v.w = tf32rf(v.w);
        ((float4*)dst)[i] = v;
    }
}

// permute q_up weights into head-interleaved rows: dst row r = h*192+d
__global__ void round_qup(const float* __restrict__ nope, const float* __restrict__ rope,
                          float* __restrict__ dst) {
    int r = blockIdx.x;            // 0..3071
    int h = r / 192, d = r - h * 192;
    const float* src = (d < 128) ? nope + (size_t)(h * 128 + d) * QLORA_
                                 : rope + (size_t)(h * 64 + d - 128) * QLORA_;
    float* o = dst + (size_t)r * QLORA_;
    for (int i = threadIdx.x; i < QLORA_ / 4; i += 256) {
        float4 v = ((const float4*)src)[i];
        v.x = tf32rf(v.x); v.y = tf32rf(v.y); v.z = tf32rf(v.z); v.w = tf32rf(v.w);
        ((float4*)o)[i] = v;
    }
}

// ---------------- tf32 tensor-core GEMM (pre-rounded operands, 3-stage) --------
// C[m,n] = sum_k A[m,k]*W[n,k]; A [M,K], W [N,K] row-major; M%128==0, K%16==0.
#define SA 20       // smem row stride (16 + 4 pad)
#define GSTG 3
#define GEMM_SMEM (GSTG * 2 * 128 * SA * 4)

__global__ void __launch_bounds__(256, 2) tf32gemm(
    const float* __restrict__ A, const float* __restrict__ W,
    float* __restrict__ C, int M, int N, int K, int ldc)
{
    extern __shared__ float sbuf[];   // [GSTG][2][128*SA]
    int tid = threadIdx.x;
    int bm = blockIdx.y * 128, bn = blockIdx.x * 128;
    int warp = tid >> 5, lane = tid & 31;
    int wm = warp >> 2, wn = warp & 3, grp = lane >> 2, qid = lane & 3;

    float acc[4][4][4];
#pragma unroll
    for (int mt = 0; mt < 4; mt++)
#pragma unroll
        for (int nt = 0; nt < 4; nt++)
#pragma unroll
            for (int i = 0; i < 4; i++) acc[mt][nt][i] = 0.f;

    int ar0 = tid >> 2;
    int aq0 = (tid & 3) * 4;
    const float* A0 = A + (size_t)(bm + ar0) * K + aq0;
    const float* A1 = A + (size_t)(bm + ar0 + 64) * K + aq0;
    int n0 = bn + ar0, n1 = bn + ar0 + 64;
    bool bv0 = n0 < N, bv1 = n1 < N;
    const float* W0 = W + (size_t)(bv0 ? n0 : (N - 1)) * K + aq0;
    const float* W1 = W + (size_t)(bv1 ? n1 : (N - 1)) * K + aq0;

    int NKt = K >> 4;

    auto prefetch = [&](int kt) {
        int s = kt % GSTG;
        float* sa = sbuf + (size_t)(s * 2) * (128 * SA);
        float* sb = sa + 128 * SA;
        int koff = kt << 4;
        cp16(&sa[ar0 * SA + aq0], A0 + koff, true);
        cp16(&sa[(ar0 + 64) * SA + aq0], A1 + koff, true);
        cp16(&sb[ar0 * SA + aq0], W0 + koff, bv0);
        cp16(&sb[(ar0 + 64) * SA + aq0], W1 + koff, bv1);
    };

    prefetch(0);
    asm volatile("cp.async.commit_group;\n");
    if (NKt > 1) prefetch(1);
    asm volatile("cp.async.commit_group;\n");

    for (int kt = 0; kt < NKt; kt++) {
        asm volatile("cp.async.wait_group 1;\n");
        __syncthreads();                 // stage kt ready; prev compute done
        if (kt + 2 < NKt) prefetch(kt + 2);
        asm volatile("cp.async.commit_group;\n");

        int s = kt % GSTG;
        const float* As_ = sbuf + (size_t)(s * 2) * (128 * SA);
        const float* Bs_ = As_ + 128 * SA;
#pragma unroll
        for (int ks = 0; ks < 2; ks++) {
            int k0 = ks * 8;
            uint32_t bf[4][2];
#pragma unroll
            for (int nt = 0; nt < 4; nt++) {
                int nb = (wn * 32 + nt * 8 + grp) * SA + k0 + qid;
                bf[nt][0] = FU(Bs_[nb]);
                bf[nt][1] = FU(Bs_[nb + 4]);
            }
#pragma unroll
            for (int mt = 0; mt < 4; mt++) {
                int mb = (wm * 64 + mt * 16 + grp) * SA + k0 + qid;
                uint32_t af[4];
                af[0] = FU(As_[mb]);
                af[1] = FU(As_[mb + 8 * SA]);
                af[2] = FU(As_[mb + 4]);
                af[3] = FU(As_[mb + 8 * SA + 4]);
#pragma unroll
                for (int nt = 0; nt < 4; nt++) mma_tf32(acc[mt][nt], af, bf[nt]);
            }
        }
    }

    int r0 = bm + wm * 64 + grp;
    int nbase = bn + wn * 32 + qid * 2;
#pragma unroll
    for (int mt = 0; mt < 4; mt++) {
#pragma unroll
        for (int nt = 0; nt < 4; nt++) {
            int n = nbase + nt * 8;
            if (n < N) {
                int row = r0 + mt * 16;
                *(float2*)&C[(size_t)row * ldc + n] =
                    make_float2(acc[mt][nt][0], acc[mt][nt][1]);
                *(float2*)&C[(size_t)(row + 8) * ldc + n] =
                    make_float2(acc[mt][nt][2], acc[mt][nt][3]);
            }
        }
    }
}

// ---------------- rmsnorm (outputs tf32-rounded) --------------------------------
__global__ void rmsnorm_kernel(float* __restrict__ xio, const float* __restrict__ w, int D) {
    size_t row = blockIdx.x;
    float* p = xio + row * (size_t)D;
    float ss = 0.f;
    for (int i = threadIdx.x; i < D; i += 256) { float v = p[i]; ss += v * v; }
    ss = block_reduce_sum_256(ss);
    float r = rsqrtf(ss / (float)D + 1e-6f);
    for (int i = threadIdx.x; i < D; i += 256) p[i] = tf32rf(p[i] * r * w[i]);
}

// ---------------- kv prep (ckv tf32-rounded) ------------------------------------
__global__ void kvprep_kernel(const float* __restrict__ raw, const float* __restrict__ w,
                              const float* __restrict__ fc, const float* __restrict__ fs,
                              float* __restrict__ ckv, float* __restrict__ kr) {
    int tok = blockIdx.x;
    const float* src = raw + (size_t)tok * 576;
    float ss = 0.f;
    for (int i = threadIdx.x; i < 512; i += 256) { float v = src[i]; ss += v * v; }
    ss = block_reduce_sum_256(ss);
    float r = rsqrtf(ss / 512.f + 1e-6f);
    for (int i = threadIdx.x; i < 512; i += 256)
        ckv[(size_t)tok * 512 + i] = tf32rf(src[i] * r * w[i]);
    if (threadIdx.x < 32) {
        int t = tok & (T_ - 1);
        int i = threadIdx.x;
        float x0 = src[512 + 2 * i], x1 = src[512 + 2 * i + 1];
        float c = fc[t * 32 + i], s = fs[t * 32 + i];
        kr[(size_t)tok * 64 + 2 * i]     = x0 * c - x1 * s;
        kr[(size_t)tok * 64 + 2 * i + 1] = x0 * s + x1 * c;
    }
}

__global__ void rope_q_kernel(float* __restrict__ q, const float* __restrict__ fc,
                              const float* __restrict__ fs) {
    int tok = blockIdx.x;
    int t = tok & (T_ - 1);
    int p = threadIdx.x;
    int h = p >> 5, i = p & 31;
    float* b = q + (size_t)tok * 3072 + h * 192 + 128;
    float x0 = b[2 * i], x1 = b[2 * i + 1];
    float c = fc[t * 32 + i], s = fs[t * 32 + i];
    b[2 * i]     = x0 * c - x1 * s;
    b[2 * i + 1] = x0 * s + x1 * c;
}

// ---------------- tensor-core flash attention (tf32, causal) -------------------
#define AQS 196
#define AKS 196
#define AVS 136
#define APS 68
#define ASM_FLOATS (64*AQS + 64*AKS + 64*AVS + 64*APS + 128 + 128)
#define ASM_BYTES (ASM_FLOATS * 4)

__global__ void __launch_bounds__(256) attn_mma_kernel(
    const float* __restrict__ q, const float* __restrict__ kv,
    const float* __restrict__ krope, float* __restrict__ out)
{
    extern __shared__ float sm[];
    float* sQ  = sm;
    float* sK  = sQ + 64 * AQS;
    float* sV  = sK + 64 * AKS;
    float* sP  = sV + 64 * AVS;
    float* sRM = sP + 64 * APS;
    float* sRL = sRM + 128;

    int b = blockIdx.z, h = blockIdx.y, qt = blockIdx.x;
    int tid = threadIdx.x;
    int warp = tid >> 5, lane = tid & 31;
    int wm = warp >> 1, wn = warp & 1;
    int grp = lane >> 2, qid = lane & 3;
    int t0 = b * T_ + qt * 64;
    int r0 = wm * 16 + grp, r1 = r0 + 8;

    const float qsc = 0.07216878364870323f * 1.4426950408889634f;

    for (int idx = tid; idx < 64 * 48; idx += 256) {
        int r = idx / 48, f = (idx - r * 48) * 4;
        float4 v = *(const float4*)&q[(size_t)(t0 + r) * 3072 + h * 192 + f];
        sQ[r * AQS + f + 0] = tf32rf(v.x * qsc);
        sQ[r * AQS + f + 1] = tf32rf(v.y * qsc);
        sQ[r * AQS + f + 2] = tf32rf(v.z * qsc);
        sQ[r * AQS + f + 3] = tf32rf(v.w * qsc);
    }

    float m0 = -1e30f, m1 = -1e30f, l0 = 0.f, l1 = 0.f;
    float accO[8][4];
#pragma unroll
    for (int nt = 0; nt < 8; nt++)
#pragma unroll
        for (int i = 0; i < 4; i++) accO[nt][i] = 0.f;

    for (int jt = 0; jt <= qt; jt++) {
        int kb = b * T_ + jt * 64;
        __syncthreads();
        for (int idx = tid; idx < 64 * 32; idx += 256) {
            int c = idx >> 5, f = idx & 31;
            const float4* src = (const float4*)&kv[(size_t)(kb + c) * 4096 + h * 256];
            float4 kk = src[f], vv = src[32 + f];
            float* kd = &sK[c * AKS + f * 4];
            kd[0] = tf32rf(kk.x); kd[1] = tf32rf(kk.y); kd[2] = tf32rf(kk.z); kd[3] = tf32rf(kk.w);
            float* vd = &sV[c * AVS + f * 4];
            vd[0] = tf32rf(vv.x); vd[1] = tf32rf(vv.y); vd[2] = tf32rf(vv.z); vd[3] = tf32rf(vv.w);
        }
        for (int idx = tid; idx < 64 * 16; idx += 256) {
            int c = idx >> 4, f = idx & 15;
            float4 kk = *(const float4*)&krope[(size_t)(kb + c) * 64 + f * 4];
            float* kd = &sK[c * AKS + 128 + f * 4];
            kd[0] = tf32rf(kk.x); kd[1] = tf32rf(kk.y); kd[2] = tf32rf(kk.z); kd[3] = tf32rf(kk.w);
        }
        __syncthreads();

        float sfr[4][4];
#pragma unroll
        for (int nt = 0; nt < 4; nt++)
#pragma unroll
            for (int i = 0; i < 4; i++) sfr[nt][i] = 0.f;
#pragma unroll 4
        for (int ks = 0; ks < 24; ks++) {
            int k0 = ks * 8;
            uint32_t af[4];
            af[0] = FU(sQ[r0 * AQS + k0 + qid]);
            af[1] = FU(sQ[r1 * AQS + k0 + qid]);
            af[2] = FU(sQ[r0 * AQS + k0 + qid + 4]);
            af[3] = FU(sQ[r1 * AQS + k0 + qid + 4]);
#pragma unroll
            for (int nt = 0; nt < 4; nt++) {
                int n = wn * 32 + nt * 8 + grp;
                uint32_t bf[2] = { FU(sK[n * AKS + k0 + qid]),
                                   FU(sK[n * AKS + k0 + qid + 4]) };
                mma_tf32(sfr[nt], af, bf);
            }
        }

        if (jt == qt) {
#pragma unroll
            for (int nt = 0; nt < 4; nt++) {
                int c0 = wn * 32 + nt * 8 + 2 * qid;
                if (c0 > r0)     sfr[nt][0] = -1e30f;
                if (c0 + 1 > r0) sfr[nt][1] = -1e30f;
                if (c0 > r1)     sfr[nt][2] = -1e30f;
                if (c0 + 1 > r1) sfr[nt][3] = -1e30f;
            }
        }

        float mx0 = -1e30f, mx1 = -1e30f;
#pragma unroll
        for (int nt = 0; nt < 4; nt++) {
            mx0 = fmaxf(mx0, fmaxf(sfr[nt][0], sfr[nt][1]));
            mx1 = fmaxf(mx1, fmaxf(sfr[nt][2], sfr[nt][3]));
        }
        mx0 = fmaxf(mx0, __shfl_xor_sync(0xffffffffu, mx0, 1));
        mx0 = fmaxf(mx0, __shfl_xor_sync(0xffffffffu, mx0, 2));
        mx1 = fmaxf(mx1, __shfl_xor_sync(0xffffffffu, mx1, 1));
        mx1 = fmaxf(mx1, __shfl_xor_sync(0xffffffffu, mx1, 2));
        if (qid == 0) { sRM[r0 * 2 + wn] = mx0; sRM[r1 * 2 + wn] = mx1; }
        __syncthreads();
        float mn0 = fmaxf(m0, fmaxf(sRM[r0 * 2], sRM[r0 * 2 + 1]));
        float mn1 = fmaxf(m1, fmaxf(sRM[r1 * 2], sRM[r1 * 2 + 1]));
        float al0 = ex2(m0 - mn0), al1 = ex2(m1 - mn1);
        m0 = mn0; m1 = mn1;

        float sum0 = 0.f, sum1 = 0.f;
#pragma unroll
        for (int nt = 0; nt < 4; nt++) {
            int c0 = wn * 32 + nt * 8 + 2 * qid;
            float p00 = ex2(sfr[nt][0] - mn0), p01 = ex2(sfr[nt][1] - mn0);
            float p10 = ex2(sfr[nt][2] - mn1), p11 = ex2(sfr[nt][3] - mn1);
            sum0 += p00 + p01;
            sum1 += p10 + p11;
            *(float2*)&sP[r0 * APS + c0] = make_float2(tf32rf(p00), tf32rf(p01));
            *(float2*)&sP[r1 * APS + c0] = make_float2(tf32rf(p10), tf32rf(p11));
        }
        sum0 += __shfl_xor_sync(0xffffffffu, sum0, 1);
        sum0 += __shfl_xor_sync(0xffffffffu, sum0, 2);
        sum1 += __shfl_xor_sync(0xffffffffu, sum1, 1);
        sum1 += __shfl_xor_sync(0xffffffffu, sum1, 2);
        l0 = l0 * al0 + sum0;
        l1 = l1 * al1 + sum1;

#pragma unroll
        for (int nt = 0; nt < 8; nt++) {
            accO[nt][0] *= al0; accO[nt][1] *= al0;
            accO[nt][2] *= al1; accO[nt][3] *= al1;
        }
        __syncthreads();

#pragma unroll
        for (int ks = 0; ks < 8; ks++) {
            int k0 = ks * 8;
            uint32_t pa[4];
            pa[0] = FU(sP[r0 * APS + k0 + qid]);
            pa[1] = FU(sP[r1 * APS + k0 + qid]);
            pa[2] = FU(sP[r0 * APS + k0 + qid + 4]);
            pa[3] = FU(sP[r1 * APS + k0 + qid + 4]);
#pragma unroll
            for (int nt = 0; nt < 8; nt++) {
                int vb = wn * 64 + nt * 8 + grp;
                uint32_t bf[2] = { FU(sV[(k0 + qid) * AVS + vb]),
                                   FU(sV[(k0 + qid + 4) * AVS + vb]) };
                mma_tf32(accO[nt], pa, bf);
            }
        }
    }

    if (qid == 0) { sRL[r0 * 2 + wn] = l0; sRL[r1 * 2 + wn] = l1; }
    __syncthreads();
    float inv0 = 1.f / (sRL[r0 * 2] + sRL[r0 * 2 + 1]);
    float inv1 = 1.f / (sRL[r1 * 2] + sRL[r1 * 2 + 1]);
#pragma unroll
    for (int nt = 0; nt < 8; nt++) {
        int col = h * 128 + wn * 64 + nt * 8 + 2 * qid;
        // pre-rounded for the wo GEMM
        *(float2*)&out[(size_t)(t0 + r0) * 2048 + col] =
            make_float2(tf32rf(accO[nt][0] * inv0), tf32rf(accO[nt][1] * inv0));
        *(float2*)&out[(size_t)(t0 + r1) * 2048 + col] =
            make_float2(tf32rf(accO[nt][2] * inv1), tf32rf(accO[nt][3] * inv1));
    }
}

// ---------------- launch -------------------------------------------------------
extern "C" void kernel_launch(void* const* d_in, const int* in_sizes, int n_in,
                              void* d_out, int out_size) {
    const float* x           = (const float*)d_in[0];
    const float* fc          = (const float*)d_in[1];
    const float* fs          = (const float*)d_in[2];
    const float* q_down_w    = (const float*)d_in[4];
    const float* q_norm_w    = (const float*)d_in[5];
    const float* q_up_nope_w = (const float*)d_in[6];
    const float* q_up_rope_w = (const float*)d_in[7];
    const float* kv_down_w   = (const float*)d_in[8];
    const float* kv_norm_w   = (const float*)d_in[9];
    const float* kv_up_w     = (const float*)d_in[10];
    const float* wo_w        = (const float*)d_in[11];
    float* out = (float*)d_out;

    float *cq, *qbuf, *kvraw, *ckv, *krope, *kvbuf, *attno;
    float *xr, *wqd, *wkd, *wqu, *wku, *wwo;
    cudaGetSymbolAddress((void**)&cq,    g_cq);
    cudaGetSymbolAddress((void**)&qbuf,  g_q);
    cudaGetSymbolAddress((void**)&kvraw, g_kvraw);
    cudaGetSymbolAddress((void**)&ckv,   g_ckv);
    cudaGetSymbolAddress((void**)&krope, g_krope);
    cudaGetSymbolAddress((void**)&kvbuf, g_kv);
    cudaGetSymbolAddress((void**)&attno, g_attno);
    cudaGetSymbolAddress((void**)&xr,    g_xr);
    cudaGetSymbolAddress((void**)&wqd,   g_w_qdown);
    cudaGetSymbolAddress((void**)&wkd,   g_w_kvdown);
    cudaGetSymbolAddress((void**)&wqu,   g_w_qup);
    cudaGetSymbolAddress((void**)&wku,   g_w_kvup);
    cudaGetSymbolAddress((void**)&wwo,   g_w_wo);

    cudaFuncSetAttribute(tf32gemm, cudaFuncAttributeMaxDynamicSharedMemorySize, GEMM_SMEM);
    cudaFuncSetAttribute(attn_mma_kernel, cudaFuncAttributeMaxDynamicSharedMemorySize, ASM_BYTES);

    dim3 blk(256);
    // pre-round all GEMM operands
    auto rc = [&](const float* s, float* d, size_t n) {
        int n4 = (int)(n / 4);
        round_copy<<<(n4 + 255) / 256, 256>>>(s, d, n4);
    };
    rc(x, xr, (size_t)MTOK * DIM_);
    rc(q_down_w, wqd, (size_t)QLORA_ * DIM_);
    rc(kv_down_w, wkd, (size_t)576 * DIM_);
    round_qup<<<3072, 256>>>(q_up_nope_w, q_up_rope_w, wqu);
    rc(kv_up_w, wku, (size_t)4096 * KVLORA_);
    rc(wo_w, wwo, (size_t)DIM_ * 2048);

    // q_down
    tf32gemm<<<dim3(QLORA_ / 128, MTOK / 128), blk, GEMM_SMEM>>>(
        xr, wqd, cq, MTOK, QLORA_, DIM_, QLORA_);
    rmsnorm_kernel<<<MTOK, 256>>>(cq, q_norm_w, QLORA_);

    // kv_down (N=576)
    tf32gemm<<<dim3(5, MTOK / 128), blk, GEMM_SMEM>>>(
        xr, wkd, kvraw, MTOK, 576, DIM_, 576);
    kvprep_kernel<<<MTOK, 256>>>(kvraw, kv_norm_w, fc, fs, ckv, krope);

    // merged q_up (N=3072, head-interleaved weights -> direct g_q layout)
    tf32gemm<<<dim3(3072 / 128, MTOK / 128), blk, GEMM_SMEM>>>(
        cq, wqu, qbuf, MTOK, 3072, QLORA_, 3072);
    rope_q_kernel<<<MTOK, 512>>>(qbuf, fc, fs);

    // kv_up
    tf32gemm<<<dim3(4096 / 128, MTOK / 128), blk, GEMM_SMEM>>>(
        ckv, wku, kvbuf, MTOK, 4096, KVLORA_, 4096);

    // attention
    attn_mma_kernel<<<dim3(T_ / 64, H_, B_), 256, ASM_BYTES>>>(qbuf, kvbuf, krope, attno);

    // wo
    tf32gemm<<<dim3(2048 / 128, MTOK / 128), blk, GEMM_SMEM>>>(
        attno, wwo, out, MTOK, 2048, 2048, 2048);
}

// round 6
// speedup vs baseline: 6.6667x; 2.0505x over previous
#include <cuda_runtime.h>
#include <cuda_fp16.h>
#include <cstdint>

// Problem constants
#define B_ 4
#define T_ 2048
#define DIM_ 2048
#define H_ 16
#define QLORA_ 1536
#define KVLORA_ 512
#define MTOK (B_ * T_)   // 8192

// ---------------- scratch (device globals; no runtime allocation) -------------
__device__ float  g_cq[(size_t)MTOK * QLORA_];        // q_down out (f32)
__device__ float  g_q[(size_t)MTOK * 3072];           // q_up out, roped (f32)
__device__ float  g_kvraw[(size_t)MTOK * 576];        // kv_down out (f32)
__device__ float  g_krope[(size_t)MTOK * 64];         // roped k_rope (f32)
// fp16 operands
__device__ __half g_xh[(size_t)MTOK * DIM_];
__device__ __half g_cqh[(size_t)MTOK * QLORA_];
__device__ __half g_ckvh[(size_t)MTOK * KVLORA_];
__device__ __half g_kvh[(size_t)MTOK * 4096];         // kv_up out (half): per head [K128|V128]
__device__ __half g_attnoh[(size_t)MTOK * 2048];
__device__ __half g_wqd[(size_t)QLORA_ * DIM_];
__device__ __half g_wkd[(size_t)576 * DIM_];
__device__ __half g_wqu[(size_t)3072 * QLORA_];       // head-interleaved
__device__ __half g_wku[(size_t)4096 * KVLORA_];
__device__ __half g_wwo[(size_t)DIM_ * 2048];

// ---------------- helpers ------------------------------------------------------
__device__ __forceinline__ float block_reduce_sum_256(float v) {
    __shared__ float red[8];
    int lane = threadIdx.x & 31, w = threadIdx.x >> 5;
#pragma unroll
    for (int o = 16; o; o >>= 1) v += __shfl_xor_sync(0xffffffffu, v, o);
    if (lane == 0) red[w] = v;
    __syncthreads();
    if (w == 0) {
        v = (lane < 8) ? red[lane] : 0.f;
#pragma unroll
        for (int o = 4; o; o >>= 1) v += __shfl_xor_sync(0xffffffffu, v, o);
        if (lane == 0) red[0] = v;
    }
    __syncthreads();
    return red[0];
}

__device__ __forceinline__ float ex2(float x) {
    float r;
    asm("ex2.approx.ftz.f32 %0, %1;" : "=f"(r) : "f"(x));
    return r;
}
__device__ __forceinline__ uint32_t smem_u32(const void* p) {
    uint32_t a;
    asm("{ .reg .u64 t; cvta.to.shared.u64 t, %1; cvt.u32.u64 %0, t; }"
        : "=r"(a) : "l"(p));
    return a;
}

#define LDMX4(r, addr) \
    asm volatile("ldmatrix.sync.aligned.m8n8.x4.shared.b16 {%0,%1,%2,%3}, [%4];" \
        : "=r"((r)[0]), "=r"((r)[1]), "=r"((r)[2]), "=r"((r)[3]) : "r"(addr))
#define LDMX4T(r, addr) \
    asm volatile("ldmatrix.sync.aligned.m8n8.x4.trans.shared.b16 {%0,%1,%2,%3}, [%4];" \
        : "=r"((r)[0]), "=r"((r)[1]), "=r"((r)[2]), "=r"((r)[3]) : "r"(addr))

__device__ __forceinline__ void mma_f16(float* c, const uint32_t* a,
                                        uint32_t b0, uint32_t b1) {
    asm volatile(
        "mma.sync.aligned.m16n8k16.row.col.f32.f16.f16.f32 "
        "{%0,%1,%2,%3},{%4,%5,%6,%7},{%8,%9},{%0,%1,%2,%3};\n"
        : "+f"(c[0]), "+f"(c[1]), "+f"(c[2]), "+f"(c[3])
        : "r"(a[0]), "r"(a[1]), "r"(a[2]), "r"(a[3]), "r"(b0), "r"(b1));
}

__device__ __forceinline__ void cpa16(uint32_t saddr, const void* src, bool v) {
    int sz = v ? 16 : 0;
    asm volatile("cp.async.cg.shared.global [%0], [%1], 16, %2;\n"
                 :: "r"(saddr), "l"(src), "r"(sz));
}

// ---------------- conversion kernels -------------------------------------------
__global__ void h_copy(const float* __restrict__ src, __half* __restrict__ dst, int n4) {
    int i = blockIdx.x * blockDim.x + threadIdx.x;
    if (i < n4) {
        float4 v = ((const float4*)src)[i];
        ((__half2*)dst)[2 * i]     = __floats2half2_rn(v.x, v.y);
        ((__half2*)dst)[2 * i + 1] = __floats2half2_rn(v.z, v.w);
    }
}

// permute q_up weights into head-interleaved rows (h*192+d), convert to half
__global__ void h_qup(const float* __restrict__ nope, const float* __restrict__ rope,
                      __half* __restrict__ dst) {
    int r = blockIdx.x;
    int h = r / 192, d = r - h * 192;
    const float* src = (d < 128) ? nope + (size_t)(h * 128 + d) * QLORA_
                                 : rope + (size_t)(h * 64 + d - 128) * QLORA_;
    __half* o = dst + (size_t)r * QLORA_;
    for (int i = threadIdx.x; i < QLORA_ / 4; i += 256) {
        float4 v = ((const float4*)src)[i];
        ((__half2*)o)[2 * i]     = __floats2half2_rn(v.x, v.y);
        ((__half2*)o)[2 * i + 1] = __floats2half2_rn(v.z, v.w);
    }
}

// ---------------- fp16 tensor-core GEMM ----------------------------------------
// C[m,n] = sum_k A[m,k]*W[n,k]; A [M,K] half, W [N,K] half.
// M%128==0, K%32==0. Tile 128x128x32, 3 stages, 8 warps (2x4), ldmatrix.
#define HAS 40                    // halves per smem row (32 + 8 pad) = 80 B
#define HTILE_B (128 * HAS * 2)   // 10240 B
#define HST_B (2 * HTILE_B)       // 20480 B
#define HST 3
#define HGEMM_SMEM (HST * HST_B)  // 61440 B

__global__ void __launch_bounds__(256, 2) hgemm(
    const __half* __restrict__ A, const __half* __restrict__ W,
    float* __restrict__ Cf, __half* __restrict__ Ch,
    int M, int N, int K, int ldc)
{
    extern __shared__ __align__(16) char hsm[];
    uint32_t sbase = smem_u32(hsm);
    int tid = threadIdx.x, warp = tid >> 5, lane = tid & 31;
    int wm = warp >> 2, wn = warp & 3, grp = lane >> 2, qid = lane & 3;
    int bm = blockIdx.y * 128, bn = blockIdx.x * 128;

    float acc[4][4][4];
#pragma unroll
    for (int mt = 0; mt < 4; mt++)
#pragma unroll
        for (int nt = 0; nt < 4; nt++)
#pragma unroll
            for (int i = 0; i < 4; i++) acc[mt][nt][i] = 0.f;

    // cp.async coordinates: 2 chunks per thread per tile (A and B each)
    int lr = tid >> 2, lc = tid & 3;          // row 0..63, chunk 0..3 (8 halves)
    const __half* Ag0 = A + (size_t)(bm + lr) * K + lc * 8;
    const __half* Ag1 = A + (size_t)(bm + lr + 64) * K + lc * 8;
    int n0 = bn + lr, n1 = bn + lr + 64;
    bool v0 = n0 < N, v1 = n1 < N;
    const __half* Wg0 = W + (size_t)(v0 ? n0 : 0) * K + lc * 8;
    const __half* Wg1 = W + (size_t)(v1 ? n1 : 0) * K + lc * 8;
    uint32_t dA0 = sbase + lr * 80 + lc * 16;
    uint32_t dA1 = dA0 + 64 * 80;
    uint32_t dB0 = dA0 + HTILE_B;
    uint32_t dB1 = dB0 + 64 * 80;

    int NK = K >> 5;

    auto prefetch = [&](int kt) {
        uint32_t off = (uint32_t)((kt % HST) * HST_B);
        int ko = kt * 32;
        cpa16(dA0 + off, Ag0 + ko, true);
        cpa16(dA1 + off, Ag1 + ko, true);
        cpa16(dB0 + off, Wg0 + ko, v0);
        cpa16(dB1 + off, Wg1 + ko, v1);
    };

    prefetch(0);
    asm volatile("cp.async.commit_group;\n");
    if (NK > 1) prefetch(1);
    asm volatile("cp.async.commit_group;\n");

    int lrow = lane & 15;
    for (int kt = 0; kt < NK; kt++) {
        asm volatile("cp.async.wait_group 1;\n");
        __syncthreads();
        if (kt + 2 < NK) prefetch(kt + 2);
        asm volatile("cp.async.commit_group;\n");

        uint32_t sA = sbase + (uint32_t)((kt % HST) * HST_B);
        uint32_t sB = sA + HTILE_B;
#pragma unroll
        for (int ks = 0; ks < 2; ks++) {
            uint32_t ko = (uint32_t)((ks * 16 + 8 * (lane >> 4)) * 2);
            uint32_t a[4][4], bfr[2][4];
#pragma unroll
            for (int mt = 0; mt < 4; mt++)
                LDMX4(a[mt], sA + (uint32_t)((wm * 64 + mt * 16 + lrow) * 80) + ko);
#pragma unroll
            for (int p = 0; p < 2; p++)
                LDMX4(bfr[p], sB + (uint32_t)((wn * 32 + p * 16 + lrow) * 80) + ko);
#pragma unroll
            for (int mt = 0; mt < 4; mt++)
#pragma unroll
                for (int nt = 0; nt < 4; nt++)
                    mma_f16(acc[mt][nt], a[mt],
                            bfr[nt >> 1][nt & 1], bfr[nt >> 1][(nt & 1) + 2]);
        }
    }

    // epilogue: c0,c1 -> (row, col..+1); c2,c3 -> (row+8, ..)
#pragma unroll
    for (int mt = 0; mt < 4; mt++) {
        int row = bm + wm * 64 + mt * 16 + grp;
#pragma unroll
        for (int nt = 0; nt < 4; nt++) {
            int n = bn + wn * 32 + nt * 8 + 2 * qid;
            if (n < N) {
                if (Cf) {
                    *(float2*)&Cf[(size_t)row * ldc + n] =
                        make_float2(acc[mt][nt][0], acc[mt][nt][1]);
                    *(float2*)&Cf[(size_t)(row + 8) * ldc + n] =
                        make_float2(acc[mt][nt][2], acc[mt][nt][3]);
                } else {
                    *(__half2*)&Ch[(size_t)row * ldc + n] =
                        __floats2half2_rn(acc[mt][nt][0], acc[mt][nt][1]);
                    *(__half2*)&Ch[(size_t)(row + 8) * ldc + n] =
                        __floats2half2_rn(acc[mt][nt][2], acc[mt][nt][3]);
                }
            }
        }
    }
}

// ---------------- rmsnorm: f32 in -> half out -----------------------------------
__global__ void rmsnorm_h(const float* __restrict__ in, __half* __restrict__ out,
                          const float* __restrict__ w, int D) {
    size_t row = blockIdx.x;
    const float* p = in + row * (size_t)D;
    __half* o = out + row * (size_t)D;
    float ss = 0.f;
    for (int i = threadIdx.x; i < D; i += 256) { float v = p[i]; ss += v * v; }
    ss = block_reduce_sum_256(ss);
    float r = rsqrtf(ss / (float)D + 1e-6f);
    for (int i = threadIdx.x; i < D; i += 256)
        o[i] = __float2half_rn(p[i] * r * w[i]);
}

// ---------------- kv prep: rmsnorm 512 -> half ckv; rope 64 -> f32 krope --------
__global__ void kvprep_h(const float* __restrict__ raw, const float* __restrict__ w,
                         const float* __restrict__ fc, const float* __restrict__ fs,
                         __half* __restrict__ ckv, float* __restrict__ kr) {
    int tok = blockIdx.x;
    const float* src = raw + (size_t)tok * 576;
    float ss = 0.f;
    for (int i = threadIdx.x; i < 512; i += 256) { float v = src[i]; ss += v * v; }
    ss = block_reduce_sum_256(ss);
    float r = rsqrtf(ss / 512.f + 1e-6f);
    for (int i = threadIdx.x; i < 512; i += 256)
        ckv[(size_t)tok * 512 + i] = __float2half_rn(src[i] * r * w[i]);
    if (threadIdx.x < 32) {
        int t = tok & (T_ - 1);
        int i = threadIdx.x;
        float x0 = src[512 + 2 * i], x1 = src[512 + 2 * i + 1];
        float c = fc[t * 32 + i], s = fs[t * 32 + i];
        kr[(size_t)tok * 64 + 2 * i]     = x0 * c - x1 * s;
        kr[(size_t)tok * 64 + 2 * i + 1] = x0 * s + x1 * c;
    }
}

__global__ void rope_q_kernel(float* __restrict__ q, const float* __restrict__ fc,
                              const float* __restrict__ fs) {
    int tok = blockIdx.x;
    int t = tok & (T_ - 1);
    int p = threadIdx.x;
    int h = p >> 5, i = p & 31;
    float* b = q + (size_t)tok * 3072 + h * 192 + 128;
    float x0 = b[2 * i], x1 = b[2 * i + 1];
    float c = fc[t * 32 + i], s = fs[t * 32 + i];
    b[2 * i]     = x0 * c - x1 * s;
    b[2 * i + 1] = x0 * s + x1 * c;
}

// ---------------- fp16 tensor-core flash attention (causal) --------------------
// Br=Bc=64, 8 warps (4 row x 2 col). S and PV via mma.m16n8k16.f16.
#define HQS 200   // halves per row (192+8) -> 400 B stride, conflict-free
#define HKS 200
#define HVS 136   // 128+8 -> 272 B
#define HPS 72    // 64+8 -> 144 B
#define ATT_SMEM ((64*HQS + 64*HKS + 64*HVS + 64*HPS) * 2 + 2 * 128 * 4)

__global__ void __launch_bounds__(256) attn_h_kernel(
    const float* __restrict__ q, const __half* __restrict__ kvh,
    const float* __restrict__ krope, __half* __restrict__ out)
{
    extern __shared__ __align__(16) char smraw[];
    __half* hQ = (__half*)smraw;
    __half* hK = hQ + 64 * HQS;
    __half* hV = hK + 64 * HKS;
    __half* hP = hV + 64 * HVS;
    float* sRM = (float*)(hP + 64 * HPS);
    float* sRL = sRM + 128;
    uint32_t uQ = smem_u32(hQ), uK = smem_u32(hK);
    uint32_t uV = smem_u32(hV), uP = smem_u32(hP);

    int b = blockIdx.z, h = blockIdx.y, qt = blockIdx.x;
    int tid = threadIdx.x;
    int warp = tid >> 5, lane = tid & 31;
    int wm = warp >> 1, wn = warp & 1;
    int grp = lane >> 2, qid = lane & 3;
    int lrow = lane & 15;
    int t0 = b * T_ + qt * 64;
    int r0 = wm * 16 + grp, r1 = r0 + 8;

    const float qsc = 0.07216878364870323f * 1.4426950408889634f;  // scale*log2e

    // Q tile [64 x 192], scale, convert to half
    for (int idx = tid; idx < 64 * 48; idx += 256) {
        int r = idx / 48, f = (idx - r * 48) * 4;
        float4 v = *(const float4*)&q[(size_t)(t0 + r) * 3072 + h * 192 + f];
        *(__half2*)&hQ[r * HQS + f]     = __floats2half2_rn(v.x * qsc, v.y * qsc);
        *(__half2*)&hQ[r * HQS + f + 2] = __floats2half2_rn(v.z * qsc, v.w * qsc);
    }

    float m0 = -1e30f, m1 = -1e30f, l0 = 0.f, l1 = 0.f;
    float accO[8][4];
#pragma unroll
    for (int nt = 0; nt < 8; nt++)
#pragma unroll
        for (int i = 0; i < 4; i++) accO[nt][i] = 0.f;

    for (int jt = 0; jt <= qt; jt++) {
        int kb = b * T_ + jt * 64;
        __syncthreads();   // prev iter done with hK/hV/hP (+first: hQ writes)
        // K nope + V from half kv buffer (direct uint4 copies)
        for (int idx = tid; idx < 64 * 16; idx += 256) {
            int c = idx >> 4, f = idx & 15;
            const uint4* src = (const uint4*)(kvh + (size_t)(kb + c) * 4096 + h * 256);
            *(uint4*)&hK[c * HKS + f * 8] = src[f];
            *(uint4*)&hV[c * HVS + f * 8] = src[16 + f];
        }
        // K rope cols 128..191 (f32 -> half)
        for (int idx = tid; idx < 64 * 16; idx += 256) {
            int c = idx >> 4, f = idx & 15;
            float4 v = *(const float4*)&krope[(size_t)(kb + c) * 64 + f * 4];
            *(__half2*)&hK[c * HKS + 128 + f * 4]     = __floats2half2_rn(v.x, v.y);
            *(__half2*)&hK[c * HKS + 128 + f * 4 + 2] = __floats2half2_rn(v.z, v.w);
        }
        __syncthreads();

        // S = Q K^T (warp tile 16x32), 12 k16-steps
        float sfr[4][4];
#pragma unroll
        for (int nt = 0; nt < 4; nt++)
#pragma unroll
            for (int i = 0; i < 4; i++) sfr[nt][i] = 0.f;
#pragma unroll
        for (int ks = 0; ks < 12; ks++) {
            uint32_t ko = (uint32_t)((ks * 16 + 8 * (lane >> 4)) * 2);
            uint32_t a[4], bfr[2][4];
            LDMX4(a, uQ + (uint32_t)((wm * 16 + lrow) * HQS * 2) + ko);
#pragma unroll
            for (int p = 0; p < 2; p++)
                LDMX4(bfr[p], uK + (uint32_t)((wn * 32 + p * 16 + lrow) * HKS * 2) + ko);
#pragma unroll
            for (int nt = 0; nt < 4; nt++)
                mma_f16(sfr[nt], a, bfr[nt >> 1][nt & 1], bfr[nt >> 1][(nt & 1) + 2]);
        }

        // causal mask (diagonal tile)
        if (jt == qt) {
#pragma unroll
            for (int nt = 0; nt < 4; nt++) {
                int c0 = wn * 32 + nt * 8 + 2 * qid;
                if (c0 > r0)     sfr[nt][0] = -1e30f;
                if (c0 + 1 > r0) sfr[nt][1] = -1e30f;
                if (c0 > r1)     sfr[nt][2] = -1e30f;
                if (c0 + 1 > r1) sfr[nt][3] = -1e30f;
            }
        }

        // row max across the 2 col-warps
        float mx0 = -1e30f, mx1 = -1e30f;
#pragma unroll
        for (int nt = 0; nt < 4; nt++) {
            mx0 = fmaxf(mx0, fmaxf(sfr[nt][0], sfr[nt][1]));
            mx1 = fmaxf(mx1, fmaxf(sfr[nt][2], sfr[nt][3]));
        }
        mx0 = fmaxf(mx0, __shfl_xor_sync(0xffffffffu, mx0, 1));
        mx0 = fmaxf(mx0, __shfl_xor_sync(0xffffffffu, mx0, 2));
        mx1 = fmaxf(mx1, __shfl_xor_sync(0xffffffffu, mx1, 1));
        mx1 = fmaxf(mx1, __shfl_xor_sync(0xffffffffu, mx1, 2));
        if (qid == 0) { sRM[r0 * 2 + wn] = mx0; sRM[r1 * 2 + wn] = mx1; }
        __syncthreads();
        float mn0 = fmaxf(m0, fmaxf(sRM[r0 * 2], sRM[r0 * 2 + 1]));
        float mn1 = fmaxf(m1, fmaxf(sRM[r1 * 2], sRM[r1 * 2 + 1]));
        float al0 = ex2(m0 - mn0), al1 = ex2(m1 - mn1);
        m0 = mn0; m1 = mn1;

        // exp (log2 domain), store P (half), partial row sums
        float sum0 = 0.f, sum1 = 0.f;
#pragma unroll
        for (int nt = 0; nt < 4; nt++) {
            int c0 = wn * 32 + nt * 8 + 2 * qid;
            float p00 = ex2(sfr[nt][0] - mn0), p01 = ex2(sfr[nt][1] - mn0);
            float p10 = ex2(sfr[nt][2] - mn1), p11 = ex2(sfr[nt][3] - mn1);
            sum0 += p00 + p01;
            sum1 += p10 + p11;
            *(__half2*)&hP[r0 * HPS + c0] = __floats2half2_rn(p00, p01);
            *(__half2*)&hP[r1 * HPS + c0] = __floats2half2_rn(p10, p11);
        }
        sum0 += __shfl_xor_sync(0xffffffffu, sum0, 1);
        sum0 += __shfl_xor_sync(0xffffffffu, sum0, 2);
        sum1 += __shfl_xor_sync(0xffffffffu, sum1, 1);
        sum1 += __shfl_xor_sync(0xffffffffu, sum1, 2);
        l0 = l0 * al0 + sum0;
        l1 = l1 * al1 + sum1;

#pragma unroll
        for (int nt = 0; nt < 8; nt++) {
            accO[nt][0] *= al0; accO[nt][1] *= al0;
            accO[nt][2] *= al1; accO[nt][3] *= al1;
        }
        __syncthreads();   // P complete

        // O += P V (warp tile 16x64), 4 k16-steps; V loaded via ldmatrix.trans
        int g = lane >> 3, ii = lane & 7;
#pragma unroll
        for (int ks = 0; ks < 4; ks++) {
            uint32_t ko = (uint32_t)((ks * 16 + 8 * (lane >> 4)) * 2);
            uint32_t pa[4];
            LDMX4(pa, uP + (uint32_t)((wm * 16 + lrow) * HPS * 2) + ko);
#pragma unroll
            for (int np = 0; np < 4; np++) {
                uint32_t vb[4];
                uint32_t va = uV + (uint32_t)(((ks * 16 + (g & 1) * 8 + ii) * HVS
                                  + wn * 64 + np * 16 + (g >> 1) * 8) * 2);
                LDMX4T(vb, va);
                mma_f16(accO[np * 2],     pa, vb[0], vb[1]);
                mma_f16(accO[np * 2 + 1], pa, vb[2], vb[3]);
            }
        }
    }

    // merge l across the 2 col-warps, normalize, write half
    if (qid == 0) { sRL[r0 * 2 + wn] = l0; sRL[r1 * 2 + wn] = l1; }
    __syncthreads();
    float inv0 = 1.f / (sRL[r0 * 2] + sRL[r0 * 2 + 1]);
    float inv1 = 1.f / (sRL[r1 * 2] + sRL[r1 * 2 + 1]);
#pragma unroll
    for (int nt = 0; nt < 8; nt++) {
        int col = h * 128 + wn * 64 + nt * 8 + 2 * qid;
        *(__half2*)&out[(size_t)(t0 + r0) * 2048 + col] =
            __floats2half2_rn(accO[nt][0] * inv0, accO[nt][1] * inv0);
        *(__half2*)&out[(size_t)(t0 + r1) * 2048 + col] =
            __floats2half2_rn(accO[nt][2] * inv1, accO[nt][3] * inv1);
    }
}

// ---------------- launch -------------------------------------------------------
extern "C" void kernel_launch(void* const* d_in, const int* in_sizes, int n_in,
                              void* d_out, int out_size) {
    const float* x           = (const float*)d_in[0];
    const float* fc          = (const float*)d_in[1];
    const float* fs          = (const float*)d_in[2];
    const float* q_down_w    = (const float*)d_in[4];
    const float* q_norm_w    = (const float*)d_in[5];
    const float* q_up_nope_w = (const float*)d_in[6];
    const float* q_up_rope_w = (const float*)d_in[7];
    const float* kv_down_w   = (const float*)d_in[8];
    const float* kv_norm_w   = (const float*)d_in[9];
    const float* kv_up_w     = (const float*)d_in[10];
    const float* wo_w        = (const float*)d_in[11];
    float* out = (float*)d_out;

    float *cq, *qbuf, *kvraw, *krope;
    __half *xh, *cqh, *ckvh, *kvh, *attnoh, *wqd, *wkd, *wqu, *wku, *wwo;
    cudaGetSymbolAddress((void**)&cq,     g_cq);
    cudaGetSymbolAddress((void**)&qbuf,   g_q);
    cudaGetSymbolAddress((void**)&kvraw,  g_kvraw);
    cudaGetSymbolAddress((void**)&krope,  g_krope);
    cudaGetSymbolAddress((void**)&xh,     g_xh);
    cudaGetSymbolAddress((void**)&cqh,    g_cqh);
    cudaGetSymbolAddress((void**)&ckvh,   g_ckvh);
    cudaGetSymbolAddress((void**)&kvh,    g_kvh);
    cudaGetSymbolAddress((void**)&attnoh, g_attnoh);
    cudaGetSymbolAddress((void**)&wqd,    g_wqd);
    cudaGetSymbolAddress((void**)&wkd,    g_wkd);
    cudaGetSymbolAddress((void**)&wqu,    g_wqu);
    cudaGetSymbolAddress((void**)&wku,    g_wku);
    cudaGetSymbolAddress((void**)&wwo,    g_wwo);

    cudaFuncSetAttribute(hgemm, cudaFuncAttributeMaxDynamicSharedMemorySize, HGEMM_SMEM);
    cudaFuncSetAttribute(attn_h_kernel, cudaFuncAttributeMaxDynamicSharedMemorySize, ATT_SMEM);

    // convert operands to fp16
    auto hc = [&](const float* s, __half* d, size_t n) {
        int n4 = (int)(n / 4);
        h_copy<<<(n4 + 255) / 256, 256>>>(s, d, n4);
    };
    hc(x, xh, (size_t)MTOK * DIM_);
    hc(q_down_w, wqd, (size_t)QLORA_ * DIM_);
    hc(kv_down_w, wkd, (size_t)576 * DIM_);
    h_qup<<<3072, 256>>>(q_up_nope_w, q_up_rope_w, wqu);
    hc(kv_up_w, wku, (size_t)4096 * KVLORA_);
    hc(wo_w, wwo, (size_t)DIM_ * 2048);

    dim3 blk(256);
    // q_down: [8192x2048] x [1536x2048] -> f32 cq
    hgemm<<<dim3(1536 / 128, MTOK / 128), blk, HGEMM_SMEM>>>(
        xh, wqd, cq, nullptr, MTOK, QLORA_, DIM_, QLORA_);
    rmsnorm_h<<<MTOK, 256>>>(cq, cqh, q_norm_w, QLORA_);

    // kv_down: N=576 -> f32 kvraw
    hgemm<<<dim3(5, MTOK / 128), blk, HGEMM_SMEM>>>(
        xh, wkd, kvraw, nullptr, MTOK, 576, DIM_, 576);
    kvprep_h<<<MTOK, 256>>>(kvraw, kv_norm_w, fc, fs, ckvh, krope);

    // merged q_up: N=3072 (head-interleaved) -> f32 qbuf
    hgemm<<<dim3(3072 / 128, MTOK / 128), blk, HGEMM_SMEM>>>(
        cqh, wqu, qbuf, nullptr, MTOK, 3072, QLORA_, 3072);
    rope_q_kernel<<<MTOK, 512>>>(qbuf, fc, fs);

    // kv_up: N=4096 -> HALF kvh (L2-friendly attention input)
    hgemm<<<dim3(4096 / 128, MTOK / 128), blk, HGEMM_SMEM>>>(
        ckvh, wku, nullptr, kvh, MTOK, 4096, KVLORA_, 4096);

    // attention -> half attno
    attn_h_kernel<<<dim3(T_ / 64, H_, B_), 256, ATT_SMEM>>>(qbuf, kvh, krope, attnoh);

    // wo: [8192x2048] x [2048x2048] -> f32 out
    hgemm<<<dim3(2048 / 128, MTOK / 128), blk, HGEMM_SMEM>>>(
        attnoh, wwo, out, nullptr, MTOK, 2048, 2048, 2048);
}

// round 7
// speedup vs baseline: 7.6447x; 1.1467x over previous
#include <cuda_runtime.h>
#include <cuda_fp16.h>
#include <cstdint>

// Problem constants
#define B_ 4
#define T_ 2048
#define DIM_ 2048
#define H_ 16
#define QLORA_ 1536
#define KVLORA_ 512
#define MTOK (B_ * T_)   // 8192

// ---------------- scratch (device globals; no runtime allocation) -------------
__device__ float  g_cq[(size_t)MTOK * QLORA_];        // q_down out (f32)
__device__ float  g_kvraw[(size_t)MTOK * 576];        // kv_down out (f32)
// fp16 buffers
__device__ __half g_xh[(size_t)MTOK * DIM_];
__device__ __half g_cqh[(size_t)MTOK * QLORA_];
__device__ __half g_ckvh[(size_t)MTOK * KVLORA_];
__device__ __half g_qh[(size_t)MTOK * 3072];          // q_up out (half, scaled, roped)
__device__ __half g_kropeh[(size_t)MTOK * 64];        // roped k_rope (half)
__device__ __half g_kvh[(size_t)MTOK * 4096];         // per head [K128|V128] (half)
__device__ __half g_attnoh[(size_t)MTOK * 2048];
__device__ __half g_wqd[(size_t)QLORA_ * DIM_];
__device__ __half g_wkd[(size_t)576 * DIM_];
__device__ __half g_wqu[(size_t)3072 * QLORA_];       // head-interleaved, pre-scaled
__device__ __half g_wku[(size_t)4096 * KVLORA_];
__device__ __half g_wwo[(size_t)DIM_ * 2048];

// ---------------- helpers ------------------------------------------------------
__device__ __forceinline__ float block_reduce_sum_256(float v) {
    __shared__ float red[8];
    int lane = threadIdx.x & 31, w = threadIdx.x >> 5;
#pragma unroll
    for (int o = 16; o; o >>= 1) v += __shfl_xor_sync(0xffffffffu, v, o);
    if (lane == 0) red[w] = v;
    __syncthreads();
    if (w == 0) {
        v = (lane < 8) ? red[lane] : 0.f;
#pragma unroll
        for (int o = 4; o; o >>= 1) v += __shfl_xor_sync(0xffffffffu, v, o);
        if (lane == 0) red[0] = v;
    }
    __syncthreads();
    return red[0];
}

__device__ __forceinline__ float ex2(float x) {
    float r;
    asm("ex2.approx.ftz.f32 %0, %1;" : "=f"(r) : "f"(x));
    return r;
}
__device__ __forceinline__ uint32_t smem_u32(const void* p) {
    uint32_t a;
    asm("{ .reg .u64 t; cvta.to.shared.u64 t, %1; cvt.u32.u64 %0, t; }"
        : "=r"(a) : "l"(p));
    return a;
}

#define LDMX4(r, addr) \
    asm volatile("ldmatrix.sync.aligned.m8n8.x4.shared.b16 {%0,%1,%2,%3}, [%4];" \
        : "=r"((r)[0]), "=r"((r)[1]), "=r"((r)[2]), "=r"((r)[3]) : "r"(addr))
#define LDMX4T(r, addr) \
    asm volatile("ldmatrix.sync.aligned.m8n8.x4.trans.shared.b16 {%0,%1,%2,%3}, [%4];" \
        : "=r"((r)[0]), "=r"((r)[1]), "=r"((r)[2]), "=r"((r)[3]) : "r"(addr))

__device__ __forceinline__ void mma_f16(float* c, const uint32_t* a,
                                        uint32_t b0, uint32_t b1) {
    asm volatile(
        "mma.sync.aligned.m16n8k16.row.col.f32.f16.f16.f32 "
        "{%0,%1,%2,%3},{%4,%5,%6,%7},{%8,%9},{%0,%1,%2,%3};\n"
        : "+f"(c[0]), "+f"(c[1]), "+f"(c[2]), "+f"(c[3])
        : "r"(a[0]), "r"(a[1]), "r"(a[2]), "r"(a[3]), "r"(b0), "r"(b1));
}

__device__ __forceinline__ void cpa16(uint32_t saddr, const void* src, bool v) {
    int sz = v ? 16 : 0;
    asm volatile("cp.async.cg.shared.global [%0], [%1], 16, %2;\n"
                 :: "r"(saddr), "l"(src), "r"(sz));
}

// ---------------- conversion kernels -------------------------------------------
__global__ void h_copy(const float* __restrict__ src, __half* __restrict__ dst, int n4) {
    int i = blockIdx.x * blockDim.x + threadIdx.x;
    if (i < n4) {
        float4 v = ((const float4*)src)[i];
        ((__half2*)dst)[2 * i]     = __floats2half2_rn(v.x, v.y);
        ((__half2*)dst)[2 * i + 1] = __floats2half2_rn(v.z, v.w);
    }
}

// q_up weights: head-interleave rows (h*192+d), fold scale*log2e, convert
#define QSC (0.07216878364870323f * 1.4426950408889634f)
__global__ void h_qup(const float* __restrict__ nope, const float* __restrict__ rope,
                      __half* __restrict__ dst) {
    int r = blockIdx.x;
    int h = r / 192, d = r - h * 192;
    const float* src = (d < 128) ? nope + (size_t)(h * 128 + d) * QLORA_
                                 : rope + (size_t)(h * 64 + d - 128) * QLORA_;
    __half* o = dst + (size_t)r * QLORA_;
    for (int i = threadIdx.x; i < QLORA_ / 4; i += 256) {
        float4 v = ((const float4*)src)[i];
        ((__half2*)o)[2 * i]     = __floats2half2_rn(v.x * QSC, v.y * QSC);
        ((__half2*)o)[2 * i + 1] = __floats2half2_rn(v.z * QSC, v.w * QSC);
    }
}

// ---------------- fp16 tensor-core GEMM (4-stage) -------------------------------
#define HAS 40                    // halves per smem row (32 + 8 pad) = 80 B
#define HTILE_B (128 * HAS * 2)   // 10240 B
#define HST_B (2 * HTILE_B)       // 20480 B
#define HST 4
#define HGEMM_SMEM (HST * HST_B)  // 81920 B

__global__ void __launch_bounds__(256, 2) hgemm(
    const __half* __restrict__ A, const __half* __restrict__ W,
    float* __restrict__ Cf, __half* __restrict__ Ch,
    int M, int N, int K, int ldc)
{
    extern __shared__ __align__(16) char hsm[];
    uint32_t sbase = smem_u32(hsm);
    int tid = threadIdx.x, warp = tid >> 5, lane = tid & 31;
    int wm = warp >> 2, wn = warp & 3, grp = lane >> 2, qid = lane & 3;
    int bm = blockIdx.y * 128, bn = blockIdx.x * 128;

    float acc[4][4][4];
#pragma unroll
    for (int mt = 0; mt < 4; mt++)
#pragma unroll
        for (int nt = 0; nt < 4; nt++)
#pragma unroll
            for (int i = 0; i < 4; i++) acc[mt][nt][i] = 0.f;

    int lr = tid >> 2, lc = tid & 3;
    const __half* Ag0 = A + (size_t)(bm + lr) * K + lc * 8;
    const __half* Ag1 = A + (size_t)(bm + lr + 64) * K + lc * 8;
    int n0 = bn + lr, n1 = bn + lr + 64;
    bool v0 = n0 < N, v1 = n1 < N;
    const __half* Wg0 = W + (size_t)(v0 ? n0 : 0) * K + lc * 8;
    const __half* Wg1 = W + (size_t)(v1 ? n1 : 0) * K + lc * 8;
    uint32_t dA0 = sbase + lr * 80 + lc * 16;
    uint32_t dA1 = dA0 + 64 * 80;
    uint32_t dB0 = dA0 + HTILE_B;
    uint32_t dB1 = dB0 + 64 * 80;

    int NK = K >> 5;

    auto prefetch = [&](int kt) {
        uint32_t off = (uint32_t)((kt % HST) * HST_B);
        int ko = kt * 32;
        cpa16(dA0 + off, Ag0 + ko, true);
        cpa16(dA1 + off, Ag1 + ko, true);
        cpa16(dB0 + off, Wg0 + ko, v0);
        cpa16(dB1 + off, Wg1 + ko, v1);
    };

#pragma unroll
    for (int i = 0; i < HST - 1; i++) {
        if (i < NK) prefetch(i);
        asm volatile("cp.async.commit_group;\n");
    }

    int lrow = lane & 15;
    for (int kt = 0; kt < NK; kt++) {
        asm volatile("cp.async.wait_group 2;\n");
        __syncthreads();
        if (kt + HST - 1 < NK) prefetch(kt + HST - 1);
        asm volatile("cp.async.commit_group;\n");

        uint32_t sA = sbase + (uint32_t)((kt % HST) * HST_B);
        uint32_t sB = sA + HTILE_B;
#pragma unroll
        for (int ks = 0; ks < 2; ks++) {
            uint32_t ko = (uint32_t)((ks * 16 + 8 * (lane >> 4)) * 2);
            uint32_t a[4][4], bfr[2][4];
#pragma unroll
            for (int mt = 0; mt < 4; mt++)
                LDMX4(a[mt], sA + (uint32_t)((wm * 64 + mt * 16 + lrow) * 80) + ko);
#pragma unroll
            for (int p = 0; p < 2; p++)
                LDMX4(bfr[p], sB + (uint32_t)((wn * 32 + p * 16 + lrow) * 80) + ko);
#pragma unroll
            for (int mt = 0; mt < 4; mt++)
#pragma unroll
                for (int nt = 0; nt < 4; nt++)
                    mma_f16(acc[mt][nt], a[mt],
                            bfr[nt >> 1][nt & 1], bfr[nt >> 1][(nt & 1) + 2]);
        }
    }

#pragma unroll
    for (int mt = 0; mt < 4; mt++) {
        int row = bm + wm * 64 + mt * 16 + grp;
#pragma unroll
        for (int nt = 0; nt < 4; nt++) {
            int n = bn + wn * 32 + nt * 8 + 2 * qid;
            if (n < N) {
                if (Cf) {
                    *(float2*)&Cf[(size_t)row * ldc + n] =
                        make_float2(acc[mt][nt][0], acc[mt][nt][1]);
                    *(float2*)&Cf[(size_t)(row + 8) * ldc + n] =
                        make_float2(acc[mt][nt][2], acc[mt][nt][3]);
                } else {
                    *(__half2*)&Ch[(size_t)row * ldc + n] =
                        __floats2half2_rn(acc[mt][nt][0], acc[mt][nt][1]);
                    *(__half2*)&Ch[(size_t)(row + 8) * ldc + n] =
                        __floats2half2_rn(acc[mt][nt][2], acc[mt][nt][3]);
                }
            }
        }
    }
}

// ---------------- rmsnorm: f32 in -> half out -----------------------------------
__global__ void rmsnorm_h(const float* __restrict__ in, __half* __restrict__ out,
                          const float* __restrict__ w, int D) {
    size_t row = blockIdx.x;
    const float* p = in + row * (size_t)D;
    __half* o = out + row * (size_t)D;
    float ss = 0.f;
    for (int i = threadIdx.x; i < D; i += 256) { float v = p[i]; ss += v * v; }
    ss = block_reduce_sum_256(ss);
    float r = rsqrtf(ss / (float)D + 1e-6f);
    for (int i = threadIdx.x; i < D; i += 256)
        o[i] = __float2half_rn(p[i] * r * w[i]);
}

// ---------------- kv prep: rmsnorm 512 -> half ckv; rope 64 -> half krope -------
__global__ void kvprep_h(const float* __restrict__ raw, const float* __restrict__ w,
                         const float* __restrict__ fc, const float* __restrict__ fs,
                         __half* __restrict__ ckv, __half* __restrict__ kr) {
    int tok = blockIdx.x;
    const float* src = raw + (size_t)tok * 576;
    float ss = 0.f;
    for (int i = threadIdx.x; i < 512; i += 256) { float v = src[i]; ss += v * v; }
    ss = block_reduce_sum_256(ss);
    float r = rsqrtf(ss / 512.f + 1e-6f);
    for (int i = threadIdx.x; i < 512; i += 256)
        ckv[(size_t)tok * 512 + i] = __float2half_rn(src[i] * r * w[i]);
    if (threadIdx.x < 32) {
        int t = tok & (T_ - 1);
        int i = threadIdx.x;
        float x0 = src[512 + 2 * i], x1 = src[512 + 2 * i + 1];
        float c = fc[t * 32 + i], s = fs[t * 32 + i];
        ((__half2*)kr)[(size_t)tok * 32 + i] =
            __floats2half2_rn(x0 * c - x1 * s, x0 * s + x1 * c);
    }
}

// rope on half q buffer, in place (values pre-scaled by QSC; rope is linear)
__global__ void rope_q_h(__half* __restrict__ q, const float* __restrict__ fc,
                         const float* __restrict__ fs) {
    int tok = blockIdx.x;
    int t = tok & (T_ - 1);
    int p = threadIdx.x;
    int h = p >> 5, i = p & 31;
    __half2* b = (__half2*)(q + (size_t)tok * 3072 + h * 192 + 128);
    float2 v = __half22float2(b[i]);
    float c = fc[t * 32 + i], s = fs[t * 32 + i];
    b[i] = __floats2half2_rn(v.x * c - v.y * s, v.x * s + v.y * c);
}

// ---------------- fp16 flash attention, Br=128, Bc=64, cp.async K/V ------------
#define AQ 200    // halves per Q/K row (192+8); 400B stride, conflict-free
#define AK 200
#define AV 136    // 128+8
#define AP 72     // 64+8
#define ATT_SMEM ((128*AQ + 2*64*AK + 2*64*AV + 128*AP) * 2)

__global__ void __launch_bounds__(256) attn2_kernel(
    const __half* __restrict__ qh, const __half* __restrict__ kvh,
    const __half* __restrict__ kroph, __half* __restrict__ out)
{
    extern __shared__ __align__(16) char smraw[];
    __half* hQ = (__half*)smraw;           // [128][AQ]
    __half* hK = hQ + 128 * AQ;            // [2][64][AK]
    __half* hV = hK + 2 * 64 * AK;         // [2][64][AV]
    __half* hP = hV + 2 * 64 * AV;         // [128][AP]
    uint32_t uQ = smem_u32(hQ), uK = smem_u32(hK);
    uint32_t uV = smem_u32(hV), uP = smem_u32(hP);

    int b = blockIdx.z, h = blockIdx.y;
    int qblk = gridDim.x - 1 - blockIdx.x;   // big-work CTAs first
    int tid = threadIdx.x;
    int warp = tid >> 5, lane = tid & 31;
    int grp = lane >> 2, qid = lane & 3, lrow = lane & 15;
    int w16 = warp * 16;
    int t0 = b * T_ + qblk * 128;
    int r0 = w16 + grp, r1 = r0 + 8;

    auto prefKV = [&](int jt) {
        int kb = b * T_ + jt * 64;
        int s = jt & 1;
        uint32_t bK = uK + (uint32_t)(s * 64 * AK * 2);
        uint32_t bV = uV + (uint32_t)(s * 64 * AV * 2);
#pragma unroll
        for (int i = 0; i < 4; i++) {      // K nope: 64 rows x 16 chunks
            int idx = tid + i * 256, c = idx >> 4, f = idx & 15;
            cpa16(bK + (uint32_t)((c * AK + f * 8) * 2),
                  kvh + (size_t)(kb + c) * 4096 + h * 256 + f * 8, true);
        }
#pragma unroll
        for (int i = 0; i < 2; i++) {      // K rope: 64 rows x 8 chunks
            int idx = tid + i * 256, c = idx >> 3, f = idx & 7;
            cpa16(bK + (uint32_t)((c * AK + 128 + f * 8) * 2),
                  kroph + (size_t)(kb + c) * 64 + f * 8, true);
        }
#pragma unroll
        for (int i = 0; i < 4; i++) {      // V: 64 rows x 16 chunks
            int idx = tid + i * 256, c = idx >> 4, f = idx & 15;
            cpa16(bV + (uint32_t)((c * AV + f * 8) * 2),
                  kvh + (size_t)(kb + c) * 4096 + h * 256 + 128 + f * 8, true);
        }
    };

    int jend = 2 * qblk + 1;
    prefKV(0);
    asm volatile("cp.async.commit_group;\n");

    // Q tile [128 x 192] (half, pre-scaled+roped)
    for (int idx = tid; idx < 128 * 24; idx += 256) {
        int r = idx / 24, f = idx - r * 24;
        *(uint4*)&hQ[r * AQ + f * 8] =
            *(const uint4*)&qh[(size_t)(t0 + r) * 3072 + h * 192 + f * 8];
    }

    float m0 = -1e30f, m1 = -1e30f, l0 = 0.f, l1 = 0.f;
    float accO[16][4];
#pragma unroll
    for (int nt = 0; nt < 16; nt++)
#pragma unroll
        for (int i = 0; i < 4; i++) accO[nt][i] = 0.f;

    for (int jt = 0; jt <= jend; jt++) {
        __syncthreads();                       // prev PV done (iter0: Q stores)
        if (jt < jend) prefKV(jt + 1);
        asm volatile("cp.async.commit_group;\n");
        if (jt < jend) { asm volatile("cp.async.wait_group 1;\n"); }
        else           { asm volatile("cp.async.wait_group 0;\n"); }
        __syncthreads();                       // tile jt visible

        int s = jt & 1;
        uint32_t bK = uK + (uint32_t)(s * 64 * AK * 2);
        uint32_t bV = uV + (uint32_t)(s * 64 * AV * 2);

        // S = Q K^T (warp tile 16x64), 12 k16-steps
        float sfr[8][4];
#pragma unroll
        for (int nt = 0; nt < 8; nt++)
#pragma unroll
            for (int i = 0; i < 4; i++) sfr[nt][i] = 0.f;
#pragma unroll
        for (int ks = 0; ks < 12; ks++) {
            uint32_t ko = (uint32_t)((ks * 16 + 8 * (lane >> 4)) * 2);
            uint32_t a[4], bfr[4][4];
            LDMX4(a, uQ + (uint32_t)((w16 + lrow) * AQ * 2) + ko);
#pragma unroll
            for (int p = 0; p < 4; p++)
                LDMX4(bfr[p], bK + (uint32_t)((p * 16 + lrow) * AK * 2) + ko);
#pragma unroll
            for (int nt = 0; nt < 8; nt++)
                mma_f16(sfr[nt], a, bfr[nt >> 1][nt & 1], bfr[nt >> 1][(nt & 1) + 2]);
        }

        // causal mask (last two tiles only)
        if (jt >= jend - 1) {
            int coff = jt * 64 - qblk * 128;
#pragma unroll
            for (int nt = 0; nt < 8; nt++) {
                int c0 = coff + nt * 8 + 2 * qid;
                if (c0 > r0)     sfr[nt][0] = -1e30f;
                if (c0 + 1 > r0) sfr[nt][1] = -1e30f;
                if (c0 > r1)     sfr[nt][2] = -1e30f;
                if (c0 + 1 > r1) sfr[nt][3] = -1e30f;
            }
        }

        // in-warp row max (rows fully owned by warp)
        float mx0 = -1e30f, mx1 = -1e30f;
#pragma unroll
        for (int nt = 0; nt < 8; nt++) {
            mx0 = fmaxf(mx0, fmaxf(sfr[nt][0], sfr[nt][1]));
            mx1 = fmaxf(mx1, fmaxf(sfr[nt][2], sfr[nt][3]));
        }
        mx0 = fmaxf(mx0, __shfl_xor_sync(0xffffffffu, mx0, 1));
        mx0 = fmaxf(mx0, __shfl_xor_sync(0xffffffffu, mx0, 2));
        mx1 = fmaxf(mx1, __shfl_xor_sync(0xffffffffu, mx1, 1));
        mx1 = fmaxf(mx1, __shfl_xor_sync(0xffffffffu, mx1, 2));
        float mn0 = fmaxf(m0, mx0), mn1 = fmaxf(m1, mx1);
        float al0 = ex2(m0 - mn0), al1 = ex2(m1 - mn1);
        m0 = mn0; m1 = mn1;

        float sum0 = 0.f, sum1 = 0.f;
#pragma unroll
        for (int nt = 0; nt < 8; nt++) {
            int c0 = nt * 8 + 2 * qid;
            float p00 = ex2(sfr[nt][0] - mn0), p01 = ex2(sfr[nt][1] - mn0);
            float p10 = ex2(sfr[nt][2] - mn1), p11 = ex2(sfr[nt][3] - mn1);
            sum0 += p00 + p01;
            sum1 += p10 + p11;
            *(__half2*)&hP[r0 * AP + c0] = __floats2half2_rn(p00, p01);
            *(__half2*)&hP[r1 * AP + c0] = __floats2half2_rn(p10, p11);
        }
        sum0 += __shfl_xor_sync(0xffffffffu, sum0, 1);
        sum0 += __shfl_xor_sync(0xffffffffu, sum0, 2);
        sum1 += __shfl_xor_sync(0xffffffffu, sum1, 1);
        sum1 += __shfl_xor_sync(0xffffffffu, sum1, 2);
        l0 = l0 * al0 + sum0;
        l1 = l1 * al1 + sum1;

#pragma unroll
        for (int nt = 0; nt < 16; nt++) {
            accO[nt][0] *= al0; accO[nt][1] *= al0;
            accO[nt][2] *= al1; accO[nt][3] *= al1;
        }
        __syncthreads();                       // P visible

        // O += P V (warp tile 16x128), 4 k16-steps; V via ldmatrix.trans
        int g = lane >> 3, ii = lane & 7;
#pragma unroll
        for (int ks = 0; ks < 4; ks++) {
            uint32_t ko = (uint32_t)((ks * 16 + 8 * (lane >> 4)) * 2);
            uint32_t pa[4];
            LDMX4(pa, uP + (uint32_t)((w16 + lrow) * AP * 2) + ko);
#pragma unroll
            for (int np = 0; np < 8; np++) {
                uint32_t vb[4];
                LDMX4T(vb, bV + (uint32_t)(((ks * 16 + (g & 1) * 8 + ii) * AV
                                  + np * 16 + (g >> 1) * 8) * 2));
                mma_f16(accO[np * 2],     pa, vb[0], vb[1]);
                mma_f16(accO[np * 2 + 1], pa, vb[2], vb[3]);
            }
        }
    }

    float inv0 = 1.f / l0, inv1 = 1.f / l1;
#pragma unroll
    for (int nt = 0; nt < 16; nt++) {
        int col = h * 128 + nt * 8 + 2 * qid;
        *(__half2*)&out[(size_t)(t0 + r0) * 2048 + col] =
            __floats2half2_rn(accO[nt][0] * inv0, accO[nt][1] * inv0);
        *(__half2*)&out[(size_t)(t0 + r1) * 2048 + col] =
            __floats2half2_rn(accO[nt][2] * inv1, accO[nt][3] * inv1);
    }
}

// ---------------- launch -------------------------------------------------------
extern "C" void kernel_launch(void* const* d_in, const int* in_sizes, int n_in,
                              void* d_out, int out_size) {
    const float* x           = (const float*)d_in[0];
    const float* fc          = (const float*)d_in[1];
    const float* fs          = (const float*)d_in[2];
    const float* q_down_w    = (const float*)d_in[4];
    const float* q_norm_w    = (const float*)d_in[5];
    const float* q_up_nope_w = (const float*)d_in[6];
    const float* q_up_rope_w = (const float*)d_in[7];
    const float* kv_down_w   = (const float*)d_in[8];
    const float* kv_norm_w   = (const float*)d_in[9];
    const float* kv_up_w     = (const float*)d_in[10];
    const float* wo_w        = (const float*)d_in[11];
    float* out = (float*)d_out;

    float *cq, *kvraw;
    __half *xh, *cqh, *ckvh, *qh, *kroph, *kvh, *attnoh, *wqd, *wkd, *wqu, *wku, *wwo;
    cudaGetSymbolAddress((void**)&cq,     g_cq);
    cudaGetSymbolAddress((void**)&kvraw,  g_kvraw);
    cudaGetSymbolAddress((void**)&xh,     g_xh);
    cudaGetSymbolAddress((void**)&cqh,    g_cqh);
    cudaGetSymbolAddress((void**)&ckvh,   g_ckvh);
    cudaGetSymbolAddress((void**)&qh,     g_qh);
    cudaGetSymbolAddress((void**)&kroph,  g_kropeh);
    cudaGetSymbolAddress((void**)&kvh,    g_kvh);
    cudaGetSymbolAddress((void**)&attnoh, g_attnoh);
    cudaGetSymbolAddress((void**)&wqd,    g_wqd);
    cudaGetSymbolAddress((void**)&wkd,    g_wkd);
    cudaGetSymbolAddress((void**)&wqu,    g_wqu);
    cudaGetSymbolAddress((void**)&wku,    g_wku);
    cudaGetSymbolAddress((void**)&wwo,    g_wwo);

    cudaFuncSetAttribute(hgemm, cudaFuncAttributeMaxDynamicSharedMemorySize, HGEMM_SMEM);
    cudaFuncSetAttribute(attn2_kernel, cudaFuncAttributeMaxDynamicSharedMemorySize, ATT_SMEM);

    auto hc = [&](const float* s, __half* d, size_t n) {
        int n4 = (int)(n / 4);
        h_copy<<<(n4 + 255) / 256, 256>>>(s, d, n4);
    };
    hc(x, xh, (size_t)MTOK * DIM_);
    hc(q_down_w, wqd, (size_t)QLORA_ * DIM_);
    hc(kv_down_w, wkd, (size_t)576 * DIM_);
    h_qup<<<3072, 256>>>(q_up_nope_w, q_up_rope_w, wqu);
    hc(kv_up_w, wku, (size_t)4096 * KVLORA_);
    hc(wo_w, wwo, (size_t)DIM_ * 2048);

    dim3 blk(256);
    // q_down -> f32 cq
    hgemm<<<dim3(1536 / 128, MTOK / 128), blk, HGEMM_SMEM>>>(
        xh, wqd, cq, nullptr, MTOK, QLORA_, DIM_, QLORA_);
    rmsnorm_h<<<MTOK, 256>>>(cq, cqh, q_norm_w, QLORA_);

    // kv_down -> f32 kvraw
    hgemm<<<dim3(5, MTOK / 128), blk, HGEMM_SMEM>>>(
        xh, wkd, kvraw, nullptr, MTOK, 576, DIM_, 576);
    kvprep_h<<<MTOK, 256>>>(kvraw, kv_norm_w, fc, fs, ckvh, kroph);

    // merged q_up -> HALF qh (scaled weights)
    hgemm<<<dim3(3072 / 128, MTOK / 128), blk, HGEMM_SMEM>>>(
        cqh, wqu, nullptr, qh, MTOK, 3072, QLORA_, 3072);
    rope_q_h<<<MTOK, 512>>>(qh, fc, fs);

    // kv_up -> HALF kvh
    hgemm<<<dim3(4096 / 128, MTOK / 128), blk, HGEMM_SMEM>>>(
        ckvh, wku, nullptr, kvh, MTOK, 4096, KVLORA_, 4096);

    // attention -> half attno
    attn2_kernel<<<dim3(T_ / 128, H_, B_), 256, ATT_SMEM>>>(qh, kvh, kroph, attnoh);

    // wo -> f32 out
    hgemm<<<dim3(2048 / 128, MTOK / 128), blk, HGEMM_SMEM>>>(
        attnoh, wwo, out, nullptr, MTOK, 2048, 2048, 2048);
}

// round 8
// speedup vs baseline: 7.9219x; 1.0363x over previous
#include <cuda_runtime.h>
#include <cuda_fp16.h>
#include <cstdint>

// Problem constants
#define B_ 4
#define T_ 2048
#define DIM_ 2048
#define H_ 16
#define QLORA_ 1536
#define KVLORA_ 512
#define MTOK (B_ * T_)   // 8192

// ---------------- scratch (device globals; no runtime allocation) -------------
__device__ __half g_xh[(size_t)MTOK * DIM_];
__device__ __half g_cqh[(size_t)MTOK * QLORA_];       // q_down out -> rmsnorm in-place
__device__ __half g_kvrawh[(size_t)MTOK * 576];       // kv_down out (half)
__device__ __half g_ckvh[(size_t)MTOK * KVLORA_];
__device__ __half g_qh[(size_t)MTOK * 3072];          // q_up out (half, scaled, roped)
__device__ __half g_kropeh[(size_t)MTOK * 64];        // roped k_rope (half)
__device__ __half g_kvh[(size_t)MTOK * 4096];         // per head [K128|V128] (half)
__device__ __half g_attnoh[(size_t)MTOK * 2048];
__device__ __half g_wqd[(size_t)QLORA_ * DIM_];
__device__ __half g_wkd[(size_t)576 * DIM_];
__device__ __half g_wqu[(size_t)3072 * QLORA_];       // head-interleaved, pre-scaled
__device__ __half g_wku[(size_t)4096 * KVLORA_];
__device__ __half g_wwo[(size_t)DIM_ * 2048];

// ---------------- helpers ------------------------------------------------------
__device__ __forceinline__ float block_reduce_sum_256(float v) {
    __shared__ float red[8];
    int lane = threadIdx.x & 31, w = threadIdx.x >> 5;
#pragma unroll
    for (int o = 16; o; o >>= 1) v += __shfl_xor_sync(0xffffffffu, v, o);
    if (lane == 0) red[w] = v;
    __syncthreads();
    if (w == 0) {
        v = (lane < 8) ? red[lane] : 0.f;
#pragma unroll
        for (int o = 4; o; o >>= 1) v += __shfl_xor_sync(0xffffffffu, v, o);
        if (lane == 0) red[0] = v;
    }
    __syncthreads();
    return red[0];
}

__device__ __forceinline__ float ex2(float x) {
    float r;
    asm("ex2.approx.ftz.f32 %0, %1;" : "=f"(r) : "f"(x));
    return r;
}
__device__ __forceinline__ uint32_t smem_u32(const void* p) {
    uint32_t a;
    asm("{ .reg .u64 t; cvta.to.shared.u64 t, %1; cvt.u32.u64 %0, t; }"
        : "=r"(a) : "l"(p));
    return a;
}
__device__ __forceinline__ uint32_t packh2(float a, float b) {
    __half2 h = __floats2half2_rn(a, b);
    return *(uint32_t*)&h;
}

#define LDMX4(r, addr) \
    asm volatile("ldmatrix.sync.aligned.m8n8.x4.shared.b16 {%0,%1,%2,%3}, [%4];" \
        : "=r"((r)[0]), "=r"((r)[1]), "=r"((r)[2]), "=r"((r)[3]) : "r"(addr))
#define LDMX4T(r, addr) \
    asm volatile("ldmatrix.sync.aligned.m8n8.x4.trans.shared.b16 {%0,%1,%2,%3}, [%4];" \
        : "=r"((r)[0]), "=r"((r)[1]), "=r"((r)[2]), "=r"((r)[3]) : "r"(addr))

__device__ __forceinline__ void mma_f16(float* c, const uint32_t* a,
                                        uint32_t b0, uint32_t b1) {
    asm volatile(
        "mma.sync.aligned.m16n8k16.row.col.f32.f16.f16.f32 "
        "{%0,%1,%2,%3},{%4,%5,%6,%7},{%8,%9},{%0,%1,%2,%3};\n"
        : "+f"(c[0]), "+f"(c[1]), "+f"(c[2]), "+f"(c[3])
        : "r"(a[0]), "r"(a[1]), "r"(a[2]), "r"(a[3]), "r"(b0), "r"(b1));
}

__device__ __forceinline__ void cpa16(uint32_t saddr, const void* src, bool v) {
    int sz = v ? 16 : 0;
    asm volatile("cp.async.cg.shared.global [%0], [%1], 16, %2;\n"
                 :: "r"(saddr), "l"(src), "r"(sz));
}

// ---------------- conversion kernels -------------------------------------------
__global__ void h_copy(const float* __restrict__ src, __half* __restrict__ dst, int n4) {
    int i = blockIdx.x * blockDim.x + threadIdx.x;
    if (i < n4) {
        float4 v = ((const float4*)src)[i];
        ((__half2*)dst)[2 * i]     = __floats2half2_rn(v.x, v.y);
        ((__half2*)dst)[2 * i + 1] = __floats2half2_rn(v.z, v.w);
    }
}

// q_up weights: head-interleave rows (h*192+d), fold scale*log2e, convert
#define QSC (0.07216878364870323f * 1.4426950408889634f)
__global__ void h_qup(const float* __restrict__ nope, const float* __restrict__ rope,
                      __half* __restrict__ dst) {
    int r = blockIdx.x;
    int h = r / 192, d = r - h * 192;
    const float* src = (d < 128) ? nope + (size_t)(h * 128 + d) * QLORA_
                                 : rope + (size_t)(h * 64 + d - 128) * QLORA_;
    __half* o = dst + (size_t)r * QLORA_;
    for (int i = threadIdx.x; i < QLORA_ / 4; i += 256) {
        float4 v = ((const float4*)src)[i];
        ((__half2*)o)[2 * i]     = __floats2half2_rn(v.x * QSC, v.y * QSC);
        ((__half2*)o)[2 * i + 1] = __floats2half2_rn(v.z * QSC, v.w * QSC);
    }
}

// ---------------- fp16 tensor-core GEMM (4-stage) -------------------------------
// C[m,n] = sum_k A[m,k]*W[n,k]. Optional fused RoPE epilogue (q_up):
// for output col n with d = n%192 >= 128, rotate (even,odd) pair by angle(t, (d-128)/2).
#define HAS 40                    // halves per smem row (32 + 8 pad) = 80 B
#define HTILE_B (128 * HAS * 2)   // 10240 B
#define HST_B (2 * HTILE_B)       // 20480 B
#define HST 4
#define HGEMM_SMEM (HST * HST_B)  // 81920 B

__global__ void __launch_bounds__(256, 2) hgemm(
    const __half* __restrict__ A, const __half* __restrict__ W,
    float* __restrict__ Cf, __half* __restrict__ Ch,
    int M, int N, int K, int ldc,
    int ropeOn, const float* __restrict__ fc, const float* __restrict__ fs)
{
    extern __shared__ __align__(16) char hsm[];
    uint32_t sbase = smem_u32(hsm);
    int tid = threadIdx.x, warp = tid >> 5, lane = tid & 31;
    int wm = warp >> 2, wn = warp & 3, grp = lane >> 2, qid = lane & 3;
    int bm = blockIdx.y * 128, bn = blockIdx.x * 128;

    float acc[4][4][4];
#pragma unroll
    for (int mt = 0; mt < 4; mt++)
#pragma unroll
        for (int nt = 0; nt < 4; nt++)
#pragma unroll
            for (int i = 0; i < 4; i++) acc[mt][nt][i] = 0.f;

    int lr = tid >> 2, lc = tid & 3;
    const __half* Ag0 = A + (size_t)(bm + lr) * K + lc * 8;
    const __half* Ag1 = A + (size_t)(bm + lr + 64) * K + lc * 8;
    int n0 = bn + lr, n1 = bn + lr + 64;
    bool v0 = n0 < N, v1 = n1 < N;
    const __half* Wg0 = W + (size_t)(v0 ? n0 : 0) * K + lc * 8;
    const __half* Wg1 = W + (size_t)(v1 ? n1 : 0) * K + lc * 8;
    uint32_t dA0 = sbase + lr * 80 + lc * 16;
    uint32_t dA1 = dA0 + 64 * 80;
    uint32_t dB0 = dA0 + HTILE_B;
    uint32_t dB1 = dB0 + 64 * 80;

    int NK = K >> 5;

    auto prefetch = [&](int kt) {
        uint32_t off = (uint32_t)((kt % HST) * HST_B);
        int ko = kt * 32;
        cpa16(dA0 + off, Ag0 + ko, true);
        cpa16(dA1 + off, Ag1 + ko, true);
        cpa16(dB0 + off, Wg0 + ko, v0);
        cpa16(dB1 + off, Wg1 + ko, v1);
    };

#pragma unroll
    for (int i = 0; i < HST - 1; i++) {
        if (i < NK) prefetch(i);
        asm volatile("cp.async.commit_group;\n");
    }

    int lrow = lane & 15;
    for (int kt = 0; kt < NK; kt++) {
        asm volatile("cp.async.wait_group 2;\n");
        __syncthreads();
        if (kt + HST - 1 < NK) prefetch(kt + HST - 1);
        asm volatile("cp.async.commit_group;\n");

        uint32_t sA = sbase + (uint32_t)((kt % HST) * HST_B);
        uint32_t sB = sA + HTILE_B;
#pragma unroll
        for (int ks = 0; ks < 2; ks++) {
            uint32_t ko = (uint32_t)((ks * 16 + 8 * (lane >> 4)) * 2);
            uint32_t a[4][4], bfr[2][4];
#pragma unroll
            for (int mt = 0; mt < 4; mt++)
                LDMX4(a[mt], sA + (uint32_t)((wm * 64 + mt * 16 + lrow) * 80) + ko);
#pragma unroll
            for (int p = 0; p < 2; p++)
                LDMX4(bfr[p], sB + (uint32_t)((wn * 32 + p * 16 + lrow) * 80) + ko);
#pragma unroll
            for (int mt = 0; mt < 4; mt++)
#pragma unroll
                for (int nt = 0; nt < 4; nt++)
                    mma_f16(acc[mt][nt], a[mt],
                            bfr[nt >> 1][nt & 1], bfr[nt >> 1][(nt & 1) + 2]);
        }
    }

#pragma unroll
    for (int mt = 0; mt < 4; mt++) {
        int row = bm + wm * 64 + mt * 16 + grp;
        int t0r = row & (T_ - 1), t1r = (row + 8) & (T_ - 1);
#pragma unroll
        for (int nt = 0; nt < 4; nt++) {
            int n = bn + wn * 32 + nt * 8 + 2 * qid;
            if (n < N) {
                float o0 = acc[mt][nt][0], o1 = acc[mt][nt][1];
                float o2 = acc[mt][nt][2], o3 = acc[mt][nt][3];
                if (ropeOn) {
                    int d = n % 192;
                    if (d >= 128) {
                        int i = (d - 128) >> 1;
                        float c0 = fc[t0r * 32 + i], s0 = fs[t0r * 32 + i];
                        float c1 = fc[t1r * 32 + i], s1 = fs[t1r * 32 + i];
                        float a0 = o0 * c0 - o1 * s0, a1 = o0 * s0 + o1 * c0;
                        float a2 = o2 * c1 - o3 * s1, a3 = o2 * s1 + o3 * c1;
                        o0 = a0; o1 = a1; o2 = a2; o3 = a3;
                    }
                }
                if (Cf) {
                    *(float2*)&Cf[(size_t)row * ldc + n] = make_float2(o0, o1);
                    *(float2*)&Cf[(size_t)(row + 8) * ldc + n] = make_float2(o2, o3);
                } else {
                    *(__half2*)&Ch[(size_t)row * ldc + n] = __floats2half2_rn(o0, o1);
                    *(__half2*)&Ch[(size_t)(row + 8) * ldc + n] = __floats2half2_rn(o2, o3);
                }
            }
        }
    }
}

// ---------------- rmsnorm in place on half --------------------------------------
__global__ void rmsnorm_h(__half* __restrict__ io, const float* __restrict__ w, int D) {
    size_t row = blockIdx.x;
    __half* p = io + row * (size_t)D;
    float ss = 0.f;
    for (int i = threadIdx.x; i < D; i += 256) {
        float v = __half2float(p[i]); ss += v * v;
    }
    ss = block_reduce_sum_256(ss);
    float r = rsqrtf(ss / (float)D + 1e-6f);
    for (int i = threadIdx.x; i < D; i += 256)
        p[i] = __float2half_rn(__half2float(p[i]) * r * w[i]);
}

// ---------------- kv prep (half in): rmsnorm 512 -> ckv; rope 64 -> krope -------
__global__ void kvprep_h(const __half* __restrict__ raw, const float* __restrict__ w,
                         const float* __restrict__ fc, const float* __restrict__ fs,
                         __half* __restrict__ ckv, __half* __restrict__ kr) {
    int tok = blockIdx.x;
    const __half* src = raw + (size_t)tok * 576;
    float ss = 0.f;
    for (int i = threadIdx.x; i < 512; i += 256) {
        float v = __half2float(src[i]); ss += v * v;
    }
    ss = block_reduce_sum_256(ss);
    float r = rsqrtf(ss / 512.f + 1e-6f);
    for (int i = threadIdx.x; i < 512; i += 256)
        ckv[(size_t)tok * 512 + i] = __float2half_rn(__half2float(src[i]) * r * w[i]);
    if (threadIdx.x < 32) {
        int t = tok & (T_ - 1);
        int i = threadIdx.x;
        float x0 = __half2float(src[512 + 2 * i]);
        float x1 = __half2float(src[512 + 2 * i + 1]);
        float c = fc[t * 32 + i], s = fs[t * 32 + i];
        ((__half2*)kr)[(size_t)tok * 32 + i] =
            __floats2half2_rn(x0 * c - x1 * s, x0 * s + x1 * c);
    }
}

// ---------------- fp16 flash attention, Br=128, Bc=64, register P --------------
#define AQ 200    // halves per Q/K row (192+8); 400B stride
#define AK 200
#define AV 136    // 128+8
#define ATT_SMEM ((128*AQ + 2*64*AK + 2*64*AV) * 2)

__global__ void __launch_bounds__(256) attn2_kernel(
    const __half* __restrict__ qh, const __half* __restrict__ kvh,
    const __half* __restrict__ kroph, __half* __restrict__ out)
{
    extern __shared__ __align__(16) char smraw[];
    __half* hQ = (__half*)smraw;           // [128][AQ]
    __half* hK = hQ + 128 * AQ;            // [2][64][AK]
    __half* hV = hK + 2 * 64 * AK;         // [2][64][AV]
    uint32_t uQ = smem_u32(hQ), uK = smem_u32(hK), uV = smem_u32(hV);

    int b = blockIdx.z, h = blockIdx.y;
    int qblk = gridDim.x - 1 - blockIdx.x;   // big-work CTAs first
    int tid = threadIdx.x;
    int warp = tid >> 5, lane = tid & 31;
    int grp = lane >> 2, qid = lane & 3, lrow = lane & 15;
    int w16 = warp * 16;
    int t0 = b * T_ + qblk * 128;
    int r0 = w16 + grp, r1 = r0 + 8;

    auto prefKV = [&](int jt) {
        int kb = b * T_ + jt * 64;
        int s = jt & 1;
        uint32_t bK = uK + (uint32_t)(s * 64 * AK * 2);
        uint32_t bV = uV + (uint32_t)(s * 64 * AV * 2);
#pragma unroll
        for (int i = 0; i < 4; i++) {      // K nope
            int idx = tid + i * 256, c = idx >> 4, f = idx & 15;
            cpa16(bK + (uint32_t)((c * AK + f * 8) * 2),
                  kvh + (size_t)(kb + c) * 4096 + h * 256 + f * 8, true);
        }
#pragma unroll
        for (int i = 0; i < 2; i++) {      // K rope
            int idx = tid + i * 256, c = idx >> 3, f = idx & 7;
            cpa16(bK + (uint32_t)((c * AK + 128 + f * 8) * 2),
                  kroph + (size_t)(kb + c) * 64 + f * 8, true);
        }
#pragma unroll
        for (int i = 0; i < 4; i++) {      // V
            int idx = tid + i * 256, c = idx >> 4, f = idx & 15;
            cpa16(bV + (uint32_t)((c * AV + f * 8) * 2),
                  kvh + (size_t)(kb + c) * 4096 + h * 256 + 128 + f * 8, true);
        }
    };

    int jend = 2 * qblk + 1;
    prefKV(0);
    asm volatile("cp.async.commit_group;\n");

    // Q tile [128 x 192]
    for (int idx = tid; idx < 128 * 24; idx += 256) {
        int r = idx / 24, f = idx - r * 24;
        *(uint4*)&hQ[r * AQ + f * 8] =
            *(const uint4*)&qh[(size_t)(t0 + r) * 3072 + h * 192 + f * 8];
    }

    float m0 = -1e30f, m1 = -1e30f, l0 = 0.f, l1 = 0.f;
    float accO[16][4];
#pragma unroll
    for (int nt = 0; nt < 16; nt++)
#pragma unroll
        for (int i = 0; i < 4; i++) accO[nt][i] = 0.f;

    for (int jt = 0; jt <= jend; jt++) {
        __syncthreads();                       // prev iter done with s^1 buffer (+iter0: Q stores)
        if (jt < jend) prefKV(jt + 1);
        asm volatile("cp.async.commit_group;\n");
        if (jt < jend) { asm volatile("cp.async.wait_group 1;\n"); }
        else           { asm volatile("cp.async.wait_group 0;\n"); }
        __syncthreads();                       // tile jt visible

        int s = jt & 1;
        uint32_t bK = uK + (uint32_t)(s * 64 * AK * 2);
        uint32_t bV = uV + (uint32_t)(s * 64 * AV * 2);

        // S = Q K^T (warp tile 16x64)
        float sfr[8][4];
#pragma unroll
        for (int nt = 0; nt < 8; nt++)
#pragma unroll
            for (int i = 0; i < 4; i++) sfr[nt][i] = 0.f;
#pragma unroll
        for (int ks = 0; ks < 12; ks++) {
            uint32_t ko = (uint32_t)((ks * 16 + 8 * (lane >> 4)) * 2);
            uint32_t a[4], bfr[4][4];
            LDMX4(a, uQ + (uint32_t)((w16 + lrow) * AQ * 2) + ko);
#pragma unroll
            for (int p = 0; p < 4; p++)
                LDMX4(bfr[p], bK + (uint32_t)((p * 16 + lrow) * AK * 2) + ko);
#pragma unroll
            for (int nt = 0; nt < 8; nt++)
                mma_f16(sfr[nt], a, bfr[nt >> 1][nt & 1], bfr[nt >> 1][(nt & 1) + 2]);
        }

        // causal mask (last two tiles)
        if (jt >= jend - 1) {
            int coff = jt * 64 - qblk * 128;
#pragma unroll
            for (int nt = 0; nt < 8; nt++) {
                int c0 = coff + nt * 8 + 2 * qid;
                if (c0 > r0)     sfr[nt][0] = -1e30f;
                if (c0 + 1 > r0) sfr[nt][1] = -1e30f;
                if (c0 > r1)     sfr[nt][2] = -1e30f;
                if (c0 + 1 > r1) sfr[nt][3] = -1e30f;
            }
        }

        // in-warp row max
        float mx0 = -1e30f, mx1 = -1e30f;
#pragma unroll
        for (int nt = 0; nt < 8; nt++) {
            mx0 = fmaxf(mx0, fmaxf(sfr[nt][0], sfr[nt][1]));
            mx1 = fmaxf(mx1, fmaxf(sfr[nt][2], sfr[nt][3]));
        }
        mx0 = fmaxf(mx0, __shfl_xor_sync(0xffffffffu, mx0, 1));
        mx0 = fmaxf(mx0, __shfl_xor_sync(0xffffffffu, mx0, 2));
        mx1 = fmaxf(mx1, __shfl_xor_sync(0xffffffffu, mx1, 1));
        mx1 = fmaxf(mx1, __shfl_xor_sync(0xffffffffu, mx1, 2));
        float mn0 = fmaxf(m0, mx0), mn1 = fmaxf(m1, mx1);
        float al0 = ex2(m0 - mn0), al1 = ex2(m1 - mn1);
        m0 = mn0; m1 = mn1;

        // exp -> register-resident P operands (FA2 layout match)
        uint32_t hp0[8], hp1[8];
        float sum0 = 0.f, sum1 = 0.f;
#pragma unroll
        for (int nt = 0; nt < 8; nt++) {
            float p00 = ex2(sfr[nt][0] - mn0), p01 = ex2(sfr[nt][1] - mn0);
            float p10 = ex2(sfr[nt][2] - mn1), p11 = ex2(sfr[nt][3] - mn1);
            sum0 += p00 + p01;
            sum1 += p10 + p11;
            hp0[nt] = packh2(p00, p01);
            hp1[nt] = packh2(p10, p11);
        }
        sum0 += __shfl_xor_sync(0xffffffffu, sum0, 1);
        sum0 += __shfl_xor_sync(0xffffffffu, sum0, 2);
        sum1 += __shfl_xor_sync(0xffffffffu, sum1, 1);
        sum1 += __shfl_xor_sync(0xffffffffu, sum1, 2);
        l0 = l0 * al0 + sum0;
        l1 = l1 * al1 + sum1;

#pragma unroll
        for (int nt = 0; nt < 16; nt++) {
            accO[nt][0] *= al0; accO[nt][1] *= al0;
            accO[nt][2] *= al1; accO[nt][3] *= al1;
        }

        // O += P V (warp tile 16x128); P from registers, V via ldmatrix.trans
        int g = lane >> 3, ii = lane & 7;
#pragma unroll
        for (int ks = 0; ks < 4; ks++) {
            uint32_t pa[4] = { hp0[2 * ks], hp1[2 * ks],
                               hp0[2 * ks + 1], hp1[2 * ks + 1] };
#pragma unroll
            for (int np = 0; np < 8; np++) {
                uint32_t vb[4];
                LDMX4T(vb, bV + (uint32_t)(((ks * 16 + (g & 1) * 8 + ii) * AV
                                  + np * 16 + (g >> 1) * 8) * 2));
                mma_f16(accO[np * 2],     pa, vb[0], vb[1]);
                mma_f16(accO[np * 2 + 1], pa, vb[2], vb[3]);
            }
        }
    }

    float inv0 = 1.f / l0, inv1 = 1.f / l1;
#pragma unroll
    for (int nt = 0; nt < 16; nt++) {
        int col = h * 128 + nt * 8 + 2 * qid;
        *(__half2*)&out[(size_t)(t0 + r0) * 2048 + col] =
            __floats2half2_rn(accO[nt][0] * inv0, accO[nt][1] * inv0);
        *(__half2*)&out[(size_t)(t0 + r1) * 2048 + col] =
            __floats2half2_rn(accO[nt][2] * inv1, accO[nt][3] * inv1);
    }
}

// ---------------- launch -------------------------------------------------------
extern "C" void kernel_launch(void* const* d_in, const int* in_sizes, int n_in,
                              void* d_out, int out_size) {
    const float* x           = (const float*)d_in[0];
    const float* fc          = (const float*)d_in[1];
    const float* fs          = (const float*)d_in[2];
    const float* q_down_w    = (const float*)d_in[4];
    const float* q_norm_w    = (const float*)d_in[5];
    const float* q_up_nope_w = (const float*)d_in[6];
    const float* q_up_rope_w = (const float*)d_in[7];
    const float* kv_down_w   = (const float*)d_in[8];
    const float* kv_norm_w   = (const float*)d_in[9];
    const float* kv_up_w     = (const float*)d_in[10];
    const float* wo_w        = (const float*)d_in[11];
    float* out = (float*)d_out;

    __half *xh, *cqh, *kvrawh, *ckvh, *qh, *kroph, *kvh, *attnoh;
    __half *wqd, *wkd, *wqu, *wku, *wwo;
    cudaGetSymbolAddress((void**)&xh,     g_xh);
    cudaGetSymbolAddress((void**)&cqh,    g_cqh);
    cudaGetSymbolAddress((void**)&kvrawh, g_kvrawh);
    cudaGetSymbolAddress((void**)&ckvh,   g_ckvh);
    cudaGetSymbolAddress((void**)&qh,     g_qh);
    cudaGetSymbolAddress((void**)&kroph,  g_kropeh);
    cudaGetSymbolAddress((void**)&kvh,    g_kvh);
    cudaGetSymbolAddress((void**)&attnoh, g_attnoh);
    cudaGetSymbolAddress((void**)&wqd,    g_wqd);
    cudaGetSymbolAddress((void**)&wkd,    g_wkd);
    cudaGetSymbolAddress((void**)&wqu,    g_wqu);
    cudaGetSymbolAddress((void**)&wku,    g_wku);
    cudaGetSymbolAddress((void**)&wwo,    g_wwo);

    cudaFuncSetAttribute(hgemm, cudaFuncAttributeMaxDynamicSharedMemorySize, HGEMM_SMEM);
    cudaFuncSetAttribute(attn2_kernel, cudaFuncAttributeMaxDynamicSharedMemorySize, ATT_SMEM);

    auto hc = [&](const float* s, __half* d, size_t n) {
        int n4 = (int)(n / 4);
        h_copy<<<(n4 + 255) / 256, 256>>>(s, d, n4);
    };
    hc(x, xh, (size_t)MTOK * DIM_);
    hc(q_down_w, wqd, (size_t)QLORA_ * DIM_);
    hc(kv_down_w, wkd, (size_t)576 * DIM_);
    h_qup<<<3072, 256>>>(q_up_nope_w, q_up_rope_w, wqu);
    hc(kv_up_w, wku, (size_t)4096 * KVLORA_);
    hc(wo_w, wwo, (size_t)DIM_ * 2048);

    dim3 blk(256);
    // q_down -> half cqh; rmsnorm in place
    hgemm<<<dim3(1536 / 128, MTOK / 128), blk, HGEMM_SMEM>>>(
        xh, wqd, nullptr, cqh, MTOK, QLORA_, DIM_, QLORA_, 0, nullptr, nullptr);
    rmsnorm_h<<<MTOK, 256>>>(cqh, q_norm_w, QLORA_);

    // kv_down -> half kvrawh
    hgemm<<<dim3(5, MTOK / 128), blk, HGEMM_SMEM>>>(
        xh, wkd, nullptr, kvrawh, MTOK, 576, DIM_, 576, 0, nullptr, nullptr);
    kvprep_h<<<MTOK, 256>>>(kvrawh, kv_norm_w, fc, fs, ckvh, kroph);

    // merged q_up -> half qh with FUSED RoPE epilogue
    hgemm<<<dim3(3072 / 128, MTOK / 128), blk, HGEMM_SMEM>>>(
        cqh, wqu, nullptr, qh, MTOK, 3072, QLORA_, 3072, 1, fc, fs);

    // kv_up -> half kvh
    hgemm<<<dim3(4096 / 128, MTOK / 128), blk, HGEMM_SMEM>>>(
        ckvh, wku, nullptr, kvh, MTOK, 4096, KVLORA_, 4096, 0, nullptr, nullptr);

    // attention -> half attno
    attn2_kernel<<<dim3(T_ / 128, H_, B_), 256, ATT_SMEM>>>(qh, kvh, kroph, attnoh);

    // wo -> f32 out
    hgemm<<<dim3(2048 / 128, MTOK / 128), blk, HGEMM_SMEM>>>(
        attnoh, wwo, out, nullptr, MTOK, 2048, 2048, 2048, 0, nullptr, nullptr);
}